// round 11
// baseline (speedup 1.0000x reference)
#include <cuda_runtime.h>
#include <cuda_bf16.h>
#include <stdint.h>

#define BB   8
#define TT   2048
#define CC   1024
#define EE   8
#define KTOP 2
#define CAPQ 320
#define HH   4096
#define BT   (BB*TT)
#define NSLOT (EE*BB*CAPQ)
#define ROWS_E (BB*CAPQ)
#define FIXCAP 256
#define FIX_THRESH 1e-3f

typedef __nv_bfloat16 bf16;
typedef long long ll;

// ---------------- scratch ----------------
__device__ bf16  g_xs  [3ll*BT*CC];
__device__ bf16  g_wr1t[3ll*CC*HH];
__device__ bf16  g_wr2t[3ll*HH*HH];
__device__ bf16  g_we1t[2ll*EE*CC*HH];
__device__ bf16  g_we2t[2ll*EE*HH*CC];
__device__ bf16  g_h1s [2ll*BT*HH];
__device__ bf16  g_h2s [2ll*BT*HH];
__device__ bf16  g_h1f [3ll*FIXCAP*HH];
__device__ bf16  g_h2f [3ll*FIXCAP*HH];
__device__ bf16  g_ehs [2ll*EE*ROWS_E*HH];
__device__ float g_ey  [(ll)EE*ROWS_E*CC];
__device__ float g_topk_p[BT*KTOP];
__device__ int   g_topk_e[BT*KTOP];
__device__ int   g_dest[BT*KTOP];
__device__ int   g_slot_tok[NSLOT];
__device__ int   g_fix_tok[FIXCAP];
__device__ int   g_fix_cnt;

// ---------------- PTX helpers ----------------
__device__ __forceinline__ uint32_t smem_u32(const void* p) {
    uint32_t a;
    asm("{ .reg .u64 t; cvta.to.shared.u64 t, %1; cvt.u32.u64 %0, t; }" : "=r"(a) : "l"(p));
    return a;
}
__device__ __forceinline__ void cp16(uint32_t dst, const void* src, int ssz) {
    asm volatile("cp.async.cg.shared.global [%0], [%1], 16, %2;" :: "r"(dst), "l"(src), "r"(ssz));
}
__device__ __forceinline__ void cp_commit() { asm volatile("cp.async.commit_group;" ::: "memory"); }
template<int N> __device__ __forceinline__ void cp_wait() {
    asm volatile("cp.async.wait_group %0;" :: "n"(N) : "memory");
}
__device__ __forceinline__ void ldsm4(uint32_t* r, uint32_t addr) {
    asm volatile("ldmatrix.sync.aligned.m8n8.x4.shared.b16 {%0,%1,%2,%3}, [%4];"
        : "=r"(r[0]), "=r"(r[1]), "=r"(r[2]), "=r"(r[3]) : "r"(addr));
}
__device__ __forceinline__ void ldsm4t(uint32_t* r, uint32_t addr) {
    asm volatile("ldmatrix.sync.aligned.m8n8.x4.trans.shared.b16 {%0,%1,%2,%3}, [%4];"
        : "=r"(r[0]), "=r"(r[1]), "=r"(r[2]), "=r"(r[3]) : "r"(addr));
}
__device__ __forceinline__ void mma_bf16(float* c, const uint32_t* a, const uint32_t* b) {
    asm volatile("mma.sync.aligned.m16n8k16.row.col.f32.bf16.bf16.f32 "
        "{%0,%1,%2,%3}, {%4,%5,%6,%7}, {%8,%9}, {%0,%1,%2,%3};"
        : "+f"(c[0]), "+f"(c[1]), "+f"(c[2]), "+f"(c[3])
        : "r"(a[0]), "r"(a[1]), "r"(a[2]), "r"(a[3]), "r"(b[0]), "r"(b[1]));
}

// ---------------- splitting helpers ----------------
__device__ __forceinline__ void split3v(float v, uint16_t* h, uint16_t* m, uint16_t* l) {
    bf16 hb = __float2bfloat16(v);
    float r1 = v - __bfloat162float(hb);
    bf16 mb = __float2bfloat16(r1);
    bf16 lb = __float2bfloat16(r1 - __bfloat162float(mb));
    *h = *(uint16_t*)&hb; *m = *(uint16_t*)&mb; *l = *(uint16_t*)&lb;
}

template<int NPL>
__global__ __launch_bounds__(256)
void splitN_kernel(const float* __restrict__ in, bf16* __restrict__ out, ll ps) {
    ll i = ((ll)blockIdx.x * 256 + threadIdx.x) * 4;
    float4 v = *(const float4*)(in + i);
    uint16_t h[4], m[4], l[4];
    split3v(v.x, h+0, m+0, l+0); split3v(v.y, h+1, m+1, l+1);
    split3v(v.z, h+2, m+2, l+2); split3v(v.w, h+3, m+3, l+3);
    *(uint2*)(out + i)      = *(uint2*)h;
    *(uint2*)(out + ps + i) = *(uint2*)m;
    if (NPL == 3) *(uint2*)(out + 2*ps + i) = *(uint2*)l;
}

// ---------------- split-bf16 GEMM via mma.sync ----------------
// Tile 128 x NT x 32, 8 warps (4m x 2n), 3-stage cp.async, single barrier per chunk.
#define PT_A 10240   // 128 rows x 80B
template<int NP, int OUTMODE, int NT>
__global__ __launch_bounds__(256, 1)
void tc_gemm(const bf16* __restrict__ A, ll ApS, int ArowsPerZ,
             const bf16* __restrict__ B, ll BpS,
             const float* __restrict__ bias, int biasPerZ,
             void* __restrict__ outp, ll OpS, int MrowsPerZ,
             const int* __restrict__ gidx, int gstride,
             int N, int K, int gm, int gn)
{
    constexpr int ROWB = NT * 2 + 16;        // B row bytes (padded)
    constexpr int PT_B = 32 * ROWB;
    constexpr int stageB = NP * (PT_A + PT_B);
    constexpr int NFR = NT / 16;             // B n-frags per warp
    constexpr int NQ  = NT / 32;             // ldsm4t per plane per ks
    constexpr int NU  = 2 * NP + 2 * NP * (NT / 128);
    constexpr int BUPP = NT * 4;             // B units per plane
    constexpr int BRU  = NT / 8;             // B 16B-units per row
    constexpr int EPS = NT + 4;

    extern __shared__ char sm[];
    __shared__ int rowtok[128];
    const uint32_t smb = smem_u32(sm);
    const int tid = threadIdx.x;
    const int wid = tid >> 5, lane = tid & 31;
    const int z = blockIdx.y;

    int bid = blockIdx.x;
    int grp = bid / (gn * 8);
    int rem = bid - grp * gn * 8;
    int gsz = gm - grp * 8; if (gsz > 8) gsz = 8;
    int mtile = grp * 8 + rem % gsz;
    int ntile = rem / gsz;
    const int m0 = mtile << 7, n0 = ntile * NT;

    if (tid < 128)
        rowtok[tid] = gidx ? gidx[(ll)z * gstride + m0 + tid] : (z * ArowsPerZ + m0 + tid);
    __syncthreads();

    const int nch = K >> 5;
    const ll KN = (ll)K * N;

    const char* srcp[NU];
    uint32_t dsto[NU];
    int ssz[NU];
    ll step[NU];
#pragma unroll
    for (int j = 0; j < NU; j++) {
        int u = tid + j * 256;
        if (u < NP * 512) {                       // A unit
            int p = u >> 9, t = u & 511, r = t >> 2, c = t & 3;
            dsto[j] = (uint32_t)(p * PT_A + r * 80 + c * 16);
            int ra = rowtok[r];
            if (ra < 0) { srcp[j] = (const char*)A; ssz[j] = 0; }
            else { srcp[j] = (const char*)(A + (ll)p * ApS + (ll)ra * K + c * 8); ssz[j] = 16; }
            step[j] = 64;
        } else {                                  // B unit
            int uu = u - NP * 512;
            int p = uu / BUPP, t = uu % BUPP, r = t / BRU, c = t % BRU;
            dsto[j] = (uint32_t)(NP * PT_A + p * PT_B + r * ROWB + c * 16);
            srcp[j] = (const char*)(B + (ll)p * BpS + (ll)z * KN + (ll)r * N + n0 + c * 8);
            ssz[j] = 16;
            step[j] = (ll)N * 64;
        }
    }

    auto load_stage = [&](int s) {
        uint32_t sb = smb + s * stageB;
#pragma unroll
        for (int j = 0; j < NU; j++) {
            cp16(sb + dsto[j], srcp[j], ssz[j]);
            srcp[j] += step[j];
        }
        cp_commit();
    };

    const int wm = wid & 3, wn = wid >> 2;
    const uint32_t a_off = (uint32_t)((wm * 32 + (lane & 15)) * 80 + (lane >> 4) * 16);
    const uint32_t b_off = (uint32_t)((lane & 15) * ROWB + (lane >> 4) * 16);

    float acc[2][NFR][4];
#pragma unroll
    for (int mt = 0; mt < 2; mt++)
#pragma unroll
        for (int nt = 0; nt < NFR; nt++)
#pragma unroll
            for (int j = 0; j < 4; j++) acc[mt][nt][j] = 0.f;

    load_stage(0);
    load_stage(1);

    int cur = 0;
    for (int i = 0; i < nch; i++) {
        if (i + 1 < nch) cp_wait<1>(); else cp_wait<0>();
        __syncthreads();
        if (i + 2 < nch) load_stage((cur + 2 >= 3) ? cur - 1 : cur + 2);

        uint32_t sbase = smb + cur * stageB;
#pragma unroll
        for (int ks = 0; ks < 2; ks++) {
            uint32_t aF[NP][2][4];
#pragma unroll
            for (int p = 0; p < NP; p++)
#pragma unroll
                for (int mt = 0; mt < 2; mt++)
                    ldsm4(aF[p][mt], sbase + p * PT_A + mt * 16 * 80 + ks * 32 + a_off);
#pragma unroll
            for (int ib = 0; ib < NP; ib++) {
                uint32_t bF[NFR][2];
#pragma unroll
                for (int q = 0; q < NQ; q++) {
                    uint32_t r4[4];
                    ldsm4t(r4, sbase + NP * PT_A + ib * PT_B + ks * 16 * ROWB
                               + (uint32_t)((wn * (NT / 2) + q * 16) * 2) + b_off);
                    bF[q*2][0] = r4[0]; bF[q*2][1] = r4[1];
                    bF[q*2+1][0] = r4[2]; bF[q*2+1][1] = r4[3];
                }
#pragma unroll
                for (int ia = 0; ia < NP; ia++) {
                    if (ia + ib >= NP) continue;
#pragma unroll
                    for (int mt = 0; mt < 2; mt++)
#pragma unroll
                        for (int nt = 0; nt < NFR; nt++)
                            mma_bf16(acc[mt][nt], aF[ia][mt], bF[nt]);
                }
            }
        }
        cur = (cur + 1 >= 3) ? 0 : cur + 1;
    }

    // ---- epilogue: stage fp32 tile in SMEM, coalesced bias/relu/split stores ----
    __syncthreads();
    float* ep = (float*)sm;
#pragma unroll
    for (int mt = 0; mt < 2; mt++) {
        int r0 = wm * 32 + mt * 16 + (lane >> 2);
#pragma unroll
        for (int nt = 0; nt < NFR; nt++) {
            int col = wn * (NT / 2) + nt * 8 + (lane & 3) * 2;
            ep[r0 * EPS + col]       = acc[mt][nt][0];
            ep[r0 * EPS + col + 1]   = acc[mt][nt][1];
            ep[(r0+8) * EPS + col]   = acc[mt][nt][2];
            ep[(r0+8) * EPS + col+1] = acc[mt][nt][3];
        }
    }
    __syncthreads();

    {
        int r = tid >> 1, half = tid & 1;
        ll row = (ll)z * MrowsPerZ + m0 + r;
        int cbase = half * (NT / 2);
        const float* bb = bias + (ll)z * biasPerZ + n0;
#pragma unroll
        for (int q = 0; q < NT / 16; q++) {
            float v[8];
#pragma unroll
            for (int j = 0; j < 8; j++)
                v[j] = ep[r * EPS + cbase + q * 8 + j] + bb[cbase + q * 8 + j];
            if (OUTMODE == 0) {
                float* o = (float*)outp + row * (ll)N + n0 + cbase + q * 8;
                float4 o0 = {v[0], v[1], v[2], v[3]};
                float4 o1 = {v[4], v[5], v[6], v[7]};
                ((float4*)o)[0] = o0; ((float4*)o)[1] = o1;
            } else {
                __align__(16) uint16_t hs[8], ms[8], ls[8];
#pragma unroll
                for (int j = 0; j < 8; j++) {
                    float vv = fmaxf(v[j], 0.f);
                    split3v(vv, hs + j, ms + j, ls + j);
                }
                bf16* o0 = (bf16*)outp + row * (ll)N + n0 + cbase + q * 8;
                *(uint4*)o0 = *(uint4*)hs;
                *(uint4*)(o0 + OpS) = *(uint4*)ms;
                if (OUTMODE == 1) *(uint4*)(o0 + 2 * OpS) = *(uint4*)ls;
            }
        }
    }
}

// ---------------- router: logits from NPL planes, softmax, top-2 ----------------
template<int NPL>
__device__ __forceinline__ void router_logits_warp(const bf16* r0, ll ps, const float* Wr3,
                                                   int lane, float* acc)
{
#pragma unroll
    for (int e = 0; e < EE; e++) acc[e] = 0.f;
    for (int k = lane * 4; k < HH; k += 128) {
        float vv[4];
#pragma unroll
        for (int h = 0; h < 2; h++) {
            __nv_bfloat162 a = *(const __nv_bfloat162*)(r0 + k + 2 * h);
            __nv_bfloat162 b = *(const __nv_bfloat162*)(r0 + ps + k + 2 * h);
            float sx = __bfloat162float(a.x) + __bfloat162float(b.x);
            float sy = __bfloat162float(a.y) + __bfloat162float(b.y);
            if (NPL == 3) {
                __nv_bfloat162 c = *(const __nv_bfloat162*)(r0 + 2 * ps + k + 2 * h);
                sx += __bfloat162float(c.x); sy += __bfloat162float(c.y);
            }
            vv[2*h+0] = sx; vv[2*h+1] = sy;
        }
#pragma unroll
        for (int j = 0; j < 4; j++) {
            const float* w = Wr3 + (ll)(k + j) * EE;
            float xv = vv[j];
#pragma unroll
            for (int e = 0; e < EE; e++) acc[e] += xv * w[e];
        }
    }
#pragma unroll
    for (int e = 0; e < EE; e++)
#pragma unroll
        for (int off = 16; off > 0; off >>= 1)
            acc[e] += __shfl_xor_sync(0xFFFFFFFFu, acc[e], off);
}

__device__ __forceinline__ void topk_write(const float* accv, const float* br3,
                                           float* tp, int* te, int tok,
                                           int* fix_tok, int* fix_cnt)
{
    float lg[EE], mx = -1e30f;
#pragma unroll
    for (int e = 0; e < EE; e++) { lg[e] = accv[e] + br3[e]; mx = fmaxf(mx, lg[e]); }
    float p[EE], s = 0.f;
#pragma unroll
    for (int e = 0; e < EE; e++) { p[e] = __expf(lg[e] - mx); s += p[e]; }
    float inv = 1.f / s;
    int i0 = 0;
#pragma unroll
    for (int e = 1; e < EE; e++) if (lg[e] > lg[i0]) i0 = e;
    int i1 = (i0 == 0) ? 1 : 0;
#pragma unroll
    for (int e = 0; e < EE; e++) if (e != i0 && lg[e] > lg[i1]) i1 = e;
    if (fix_tok) {
        float l3 = -1e30f;
#pragma unroll
        for (int e = 0; e < EE; e++) if (e != i0 && e != i1) l3 = fmaxf(l3, lg[e]);
        if (lg[i1] - l3 < FIX_THRESH) {
            int ix = atomicAdd(fix_cnt, 1);
            if (ix < FIXCAP) fix_tok[ix] = tok;
        }
    }
    tp[tok * 2 + 0] = p[i0] * inv;
    tp[tok * 2 + 1] = p[i1] * inv;
    te[tok * 2 + 0] = i0;
    te[tok * 2 + 1] = i1;
}

__global__ __launch_bounds__(128)
void router_topk2_kernel(const bf16* __restrict__ h2s, ll ps,
                         const float* __restrict__ Wr3, const float* __restrict__ br3,
                         float* __restrict__ tp, int* __restrict__ te,
                         int* __restrict__ fix_tok, int* __restrict__ fix_cnt)
{
    int tok = (blockIdx.x * blockDim.x + threadIdx.x) >> 5;
    int lane = threadIdx.x & 31;
    if (tok >= BT) return;
    float acc[EE];
    router_logits_warp<2>(h2s + (ll)tok * HH, ps, Wr3, lane, acc);
    if (lane == 0) topk_write(acc, br3, tp, te, tok, fix_tok, fix_cnt);
}

__global__ __launch_bounds__(128)
void router_fix_kernel(const bf16* __restrict__ h2f, ll ps,
                       const float* __restrict__ Wr3, const float* __restrict__ br3,
                       const int* __restrict__ fix_tok,
                       float* __restrict__ tp, int* __restrict__ te)
{
    int r = (blockIdx.x * blockDim.x + threadIdx.x) >> 5;
    int lane = threadIdx.x & 31;
    if (r >= FIXCAP) return;
    int tok = fix_tok[r];
    if (tok < 0) return;
    float acc[EE];
    router_logits_warp<3>(h2f + (ll)r * HH, ps, Wr3, lane, acc);
    if (lane == 0) topk_write(acc, br3, tp, te, tok, nullptr, nullptr);
}

__global__ void init_fix_kernel(int* fix_tok, int* fix_cnt, int* slot_tok) {
    int i = blockIdx.x * 256 + threadIdx.x;
    if (i < FIXCAP) fix_tok[i] = -1;
    if (i == 0) *fix_cnt = 0;
    if (i < NSLOT) slot_tok[i] = -1;
}

__global__ __launch_bounds__(256)
void route_scan_kernel(const int* __restrict__ te, int* __restrict__ dest, int* __restrict__ slot_tok)
{
    __shared__ int se[TT * KTOP];
    int b = blockIdx.x;
    for (int i = threadIdx.x; i < TT * KTOP; i += 256) se[i] = te[b * TT * KTOP + i];
    __syncthreads();
    if (threadIdx.x < EE) {
        int e = threadIdx.x, cnt = 0;
        for (int i = 0; i < TT * KTOP; i++) {
            if (se[i] == e) {
                int gi = b * TT * KTOP + i;
                if (cnt < CAPQ) {
                    int s = e * (BB * CAPQ) + b * CAPQ + cnt;
                    dest[gi] = s;
                    slot_tok[s] = b * TT + (i >> 1);
                } else dest[gi] = -1;
                cnt++;
            }
        }
    }
}

__global__ __launch_bounds__(256)
void combine_kernel(const float* __restrict__ ey, const float* __restrict__ topk_p,
                    const int* __restrict__ dest, float* __restrict__ out)
{
    int tok = blockIdx.x;
    int c = threadIdx.x * 4;
    float4 r = make_float4(0.f, 0.f, 0.f, 0.f);
#pragma unroll
    for (int k = 0; k < KTOP; k++) {
        int s = dest[tok * 2 + k];
        if (s >= 0) {
            float p = topk_p[tok * 2 + k];
            float4 v = *(const float4*)(ey + (ll)s * CC + c);
            r.x += p * v.x; r.y += p * v.y; r.z += p * v.z; r.w += p * v.w;
        }
    }
    *(float4*)(out + (ll)tok * CC + c) = r;
}

// ---------------- launch ----------------
extern "C" void kernel_launch(void* const* d_in, const int* in_sizes, int n_in,
                              void* d_out, int out_size)
{
    (void)in_sizes; (void)n_in; (void)out_size;
    const float* x   = (const float*)d_in[0];
    const float* Wr1 = (const float*)d_in[1];
    const float* br1 = (const float*)d_in[2];
    const float* Wr2 = (const float*)d_in[3];
    const float* br2 = (const float*)d_in[4];
    const float* Wr3 = (const float*)d_in[5];
    const float* br3 = (const float*)d_in[6];
    const float* We1 = (const float*)d_in[7];
    const float* be1 = (const float*)d_in[8];
    const float* We2 = (const float*)d_in[9];
    const float* be2 = (const float*)d_in[10];
    float* out = (float*)d_out;

    bf16 *xs, *wr1t, *wr2t, *we1t, *we2t, *h1s, *h2s, *h1f, *h2f, *ehs;
    float *ey, *tp; int *te, *dest, *stok, *ftok, *fcnt;
    cudaGetSymbolAddress((void**)&xs,   g_xs);
    cudaGetSymbolAddress((void**)&wr1t, g_wr1t);
    cudaGetSymbolAddress((void**)&wr2t, g_wr2t);
    cudaGetSymbolAddress((void**)&we1t, g_we1t);
    cudaGetSymbolAddress((void**)&we2t, g_we2t);
    cudaGetSymbolAddress((void**)&h1s,  g_h1s);
    cudaGetSymbolAddress((void**)&h2s,  g_h2s);
    cudaGetSymbolAddress((void**)&h1f,  g_h1f);
    cudaGetSymbolAddress((void**)&h2f,  g_h2f);
    cudaGetSymbolAddress((void**)&ehs,  g_ehs);
    cudaGetSymbolAddress((void**)&ey,   g_ey);
    cudaGetSymbolAddress((void**)&tp,   g_topk_p);
    cudaGetSymbolAddress((void**)&te,   g_topk_e);
    cudaGetSymbolAddress((void**)&dest, g_dest);
    cudaGetSymbolAddress((void**)&stok, g_slot_tok);
    cudaGetSymbolAddress((void**)&ftok, g_fix_tok);
    cudaGetSymbolAddress((void**)&fcnt, g_fix_cnt);

    // smem sizes: NT=256/NP=2: 3*(2*10240 + 2*16896) = 162816 ; NT=128/NP=3: 170496
    const int SM2_256 = 3 * 2 * (10240 + 16896);
    const int SM3_128 = 3 * 3 * (10240 + 8704);
    static int smem_set = 0;
    if (!smem_set) {
        cudaFuncSetAttribute(tc_gemm<2,2,256>, cudaFuncAttributeMaxDynamicSharedMemorySize, SM2_256);
        cudaFuncSetAttribute(tc_gemm<2,0,256>, cudaFuncAttributeMaxDynamicSharedMemorySize, SM2_256);
        cudaFuncSetAttribute(tc_gemm<3,1,128>, cudaFuncAttributeMaxDynamicSharedMemorySize, SM3_128);
        smem_set = 1;
    }

    // 0) elementwise splits + table init
    splitN_kernel<3><<<(ll)BT * CC / 1024, 256>>>(x,   xs,   (ll)BT * CC);
    splitN_kernel<3><<<(ll)CC * HH / 1024, 256>>>(Wr1, wr1t, (ll)CC * HH);
    splitN_kernel<3><<<(ll)HH * HH / 1024, 256>>>(Wr2, wr2t, (ll)HH * HH);
    splitN_kernel<2><<<(ll)EE * CC * HH / 1024, 256>>>(We1, we1t, (ll)EE * CC * HH);
    splitN_kernel<2><<<(ll)EE * HH * CC / 1024, 256>>>(We2, we2t, (ll)EE * HH * CC);
    init_fix_kernel<<<(NSLOT + 255) / 256, 256>>>(ftok, fcnt, stok);

    // 1) h1 = relu(x @ Wr1 + br1) : split2 out
    tc_gemm<2,2,256><<<dim3((BT/128)*(HH/256), 1), 256, SM2_256>>>(
        xs, (ll)BT*CC, BT, wr1t, (ll)CC*HH, br1, 0,
        h1s, (ll)BT*HH, BT, nullptr, 0, HH, CC, BT/128, HH/256);

    // 2) h2 = relu(h1 @ Wr2 + br2) : split2 out
    tc_gemm<2,2,256><<<dim3((BT/128)*(HH/256), 1), 256, SM2_256>>>(
        h1s, (ll)BT*HH, BT, wr2t, (ll)HH*HH, br2, 0,
        h2s, (ll)BT*HH, BT, nullptr, 0, HH, HH, BT/128, HH/256);

    // 3) logits -> softmax -> top-2, flag marginal tokens
    router_topk2_kernel<<<(BT * 32) / 128, 128>>>(h2s, (ll)BT*HH, Wr3, br3, tp, te, ftok, fcnt);

    // 3b) exact (split3) fixup chain for flagged tokens
    tc_gemm<3,1,128><<<dim3((FIXCAP/128)*(HH/128), 1), 256, SM3_128>>>(
        xs, (ll)BT*CC, FIXCAP, wr1t, (ll)CC*HH, br1, 0,
        h1f, (ll)FIXCAP*HH, FIXCAP, ftok, FIXCAP, HH, CC, FIXCAP/128, HH/128);
    tc_gemm<3,1,128><<<dim3((FIXCAP/128)*(HH/128), 1), 256, SM3_128>>>(
        h1f, (ll)FIXCAP*HH, FIXCAP, wr2t, (ll)HH*HH, br2, 0,
        h2f, (ll)FIXCAP*HH, FIXCAP, nullptr, 0, HH, HH, FIXCAP/128, HH/128);
    router_fix_kernel<<<(FIXCAP * 32) / 128, 128>>>(h2f, (ll)FIXCAP*HH, Wr3, br3, ftok, tp, te);

    // 4) routing tables
    route_scan_kernel<<<BB, 256>>>(te, dest, stok);

    // 5) eh[e] = relu(gather(x) @ We1[e] + be1[e]) : split2 out
    tc_gemm<2,2,256><<<dim3((ROWS_E/128)*(HH/256), EE), 256, SM2_256>>>(
        xs, (ll)BT*CC, ROWS_E, we1t, (ll)EE*CC*HH, be1, HH,
        ehs, (ll)EE*ROWS_E*HH, ROWS_E, stok, ROWS_E, HH, CC, ROWS_E/128, HH/256);

    // 6) ey[e] = eh[e] @ We2[e] + be2[e] : fp32 out
    tc_gemm<2,0,256><<<dim3((ROWS_E/128)*(CC/256), EE), 256, SM2_256>>>(
        ehs, (ll)EE*ROWS_E*HH, ROWS_E, we2t, (ll)EE*HH*CC, be2, CC,
        ey, 0, ROWS_E, nullptr, 0, CC, HH, ROWS_E/128, CC/256);

    // 7) combine
    combine_kernel<<<BT, 256>>>(ey, tp, dest, out);
}

// round 12
// speedup vs baseline: 1.4892x; 1.4892x over previous
#include <cuda_runtime.h>
#include <cuda_bf16.h>
#include <stdint.h>

#define BB   8
#define TT   2048
#define CC   1024
#define EE   8
#define KTOP 2
#define CAPQ 320
#define HH   4096
#define BT   (BB*TT)
#define NSLOT (EE*BB*CAPQ)
#define ROWS_E (BB*CAPQ)
#define FIXCAP 256
#define FIX_THRESH 1e-3f

typedef __nv_bfloat16 bf16;
typedef long long ll;

// ---------------- scratch ----------------
__device__ bf16  g_xs  [3ll*BT*CC];
__device__ bf16  g_wr1t[3ll*CC*HH];
__device__ bf16  g_wr2t[3ll*HH*HH];
__device__ bf16  g_we1t[2ll*EE*CC*HH];
__device__ bf16  g_we2t[2ll*EE*HH*CC];
__device__ bf16  g_h1s [2ll*BT*HH];
__device__ bf16  g_h2s [2ll*BT*HH];
__device__ bf16  g_h1f [3ll*FIXCAP*HH];
__device__ bf16  g_h2f [3ll*FIXCAP*HH];
__device__ bf16  g_ehs [2ll*EE*ROWS_E*HH];
__device__ float g_ey  [(ll)EE*ROWS_E*CC];
__device__ float g_topk_p[BT*KTOP];
__device__ int   g_topk_e[BT*KTOP];
__device__ int   g_dest[BT*KTOP];
__device__ int   g_slot_tok[NSLOT];
__device__ int   g_fix_tok[FIXCAP];
__device__ int   g_fix_cnt;

// ---------------- PTX helpers ----------------
__device__ __forceinline__ uint32_t smem_u32(const void* p) {
    uint32_t a;
    asm("{ .reg .u64 t; cvta.to.shared.u64 t, %1; cvt.u32.u64 %0, t; }" : "=r"(a) : "l"(p));
    return a;
}
__device__ __forceinline__ void cp16(uint32_t dst, const void* src, int ssz) {
    asm volatile("cp.async.cg.shared.global [%0], [%1], 16, %2;" :: "r"(dst), "l"(src), "r"(ssz));
}
__device__ __forceinline__ void cp_commit() { asm volatile("cp.async.commit_group;" ::: "memory"); }
template<int N> __device__ __forceinline__ void cp_wait() {
    asm volatile("cp.async.wait_group %0;" :: "n"(N) : "memory");
}
__device__ __forceinline__ void ldsm4(uint32_t* r, uint32_t addr) {
    asm volatile("ldmatrix.sync.aligned.m8n8.x4.shared.b16 {%0,%1,%2,%3}, [%4];"
        : "=r"(r[0]), "=r"(r[1]), "=r"(r[2]), "=r"(r[3]) : "r"(addr));
}
__device__ __forceinline__ void ldsm4t(uint32_t* r, uint32_t addr) {
    asm volatile("ldmatrix.sync.aligned.m8n8.x4.trans.shared.b16 {%0,%1,%2,%3}, [%4];"
        : "=r"(r[0]), "=r"(r[1]), "=r"(r[2]), "=r"(r[3]) : "r"(addr));
}
__device__ __forceinline__ void mma_bf16(float* c, const uint32_t* a, const uint32_t* b) {
    asm volatile("mma.sync.aligned.m16n8k16.row.col.f32.bf16.bf16.f32 "
        "{%0,%1,%2,%3}, {%4,%5,%6,%7}, {%8,%9}, {%0,%1,%2,%3};"
        : "+f"(c[0]), "+f"(c[1]), "+f"(c[2]), "+f"(c[3])
        : "r"(a[0]), "r"(a[1]), "r"(a[2]), "r"(a[3]), "r"(b[0]), "r"(b[1]));
}

// ---------------- splitting helpers ----------------
__device__ __forceinline__ void split3v(float v, uint16_t* h, uint16_t* m, uint16_t* l) {
    bf16 hb = __float2bfloat16(v);
    float r1 = v - __bfloat162float(hb);
    bf16 mb = __float2bfloat16(r1);
    bf16 lb = __float2bfloat16(r1 - __bfloat162float(mb));
    *h = *(uint16_t*)&hb; *m = *(uint16_t*)&mb; *l = *(uint16_t*)&lb;
}

template<int NPL>
__global__ __launch_bounds__(256)
void splitN_kernel(const float* __restrict__ in, bf16* __restrict__ out, ll ps) {
    ll i = ((ll)blockIdx.x * 256 + threadIdx.x) * 4;
    float4 v = *(const float4*)(in + i);
    uint16_t h[4], m[4], l[4];
    split3v(v.x, h+0, m+0, l+0); split3v(v.y, h+1, m+1, l+1);
    split3v(v.z, h+2, m+2, l+2); split3v(v.w, h+3, m+3, l+3);
    *(uint2*)(out + i)      = *(uint2*)h;
    *(uint2*)(out + ps + i) = *(uint2*)m;
    if (NPL == 3) *(uint2*)(out + 2*ps + i) = *(uint2*)l;
}

// ---------------- split-bf16 GEMM via mma.sync ----------------
// Tile 128x128x32, 8 warps (4m x 2n), NSTG-stage cp.async ring, 1 barrier/chunk.
#define PT_A 10240   // 128 rows x 80B
#define PT_B 8704    // 32 rows x 272B
template<int NP, int OUTMODE, int NSTG>
__global__ __launch_bounds__(256, 1)
void tc_gemm(const bf16* __restrict__ A, ll ApS, int ArowsPerZ,
             const bf16* __restrict__ B, ll BpS,
             const float* __restrict__ bias, int biasPerZ,
             void* __restrict__ outp, ll OpS, int MrowsPerZ,
             const int* __restrict__ gidx, int gstride,
             int N, int K, int gm, int gn)
{
    constexpr int stageB = NP * (PT_A + PT_B);
    constexpr int NA = 2 * NP;   // A cp16 units per thread
    constexpr int NB = 2 * NP;   // B cp16 units per thread

    extern __shared__ char sm[];
    __shared__ int rowtok[128];
    const uint32_t smb = smem_u32(sm);
    const int tid = threadIdx.x;
    const int wid = tid >> 5, lane = tid & 31;
    const int z = blockIdx.y;

    int bid = blockIdx.x;
    int grp = bid / (gn * 8);
    int rem = bid - grp * gn * 8;
    int gsz = gm - grp * 8; if (gsz > 8) gsz = 8;
    int mtile = grp * 8 + rem % gsz;
    int ntile = rem / gsz;
    const int m0 = mtile << 7, n0 = ntile << 7;

    if (tid < 128)
        rowtok[tid] = gidx ? gidx[(ll)z * gstride + m0 + tid] : (z * ArowsPerZ + m0 + tid);
    __syncthreads();

    const int nch = K >> 5;
    const ll KN = (ll)K * N;
    const ll bstep = (ll)N * 64;

    // --- hoisted per-thread load state (slim) ---
    const char* srcA[NA]; uint32_t dstA[NA]; uint32_t amask = 0;
    const char* srcB[NB]; uint32_t dstB[NB];
#pragma unroll
    for (int j = 0; j < NA; j++) {
        int u = tid + j * 256;
        int p = u >> 9, t = u & 511, r = t >> 2, c = t & 3;
        dstA[j] = (uint32_t)(p * PT_A + r * 80 + c * 16);
        int ra = rowtok[r];
        if (ra < 0) srcA[j] = (const char*)A;
        else { srcA[j] = (const char*)(A + (ll)p * ApS + (ll)ra * K + c * 8); amask |= 1u << j; }
    }
#pragma unroll
    for (int j = 0; j < NB; j++) {
        int u = tid + j * 256;
        int p = u >> 9, t = u & 511, r = t >> 4, c = t & 15;
        dstB[j] = (uint32_t)(NP * PT_A + p * PT_B + r * 272 + c * 16);
        srcB[j] = (const char*)(B + (ll)p * BpS + (ll)z * KN + (ll)r * N + n0 + c * 8);
    }

    auto load_stage = [&](int s) {
        uint32_t sb = smb + s * stageB;
#pragma unroll
        for (int j = 0; j < NA; j++) {
            cp16(sb + dstA[j], srcA[j], (amask >> j & 1) ? 16 : 0);
            srcA[j] += 64;
        }
#pragma unroll
        for (int j = 0; j < NB; j++) {
            cp16(sb + dstB[j], srcB[j], 16);
            srcB[j] += bstep;
        }
        cp_commit();
    };

    const int wm = wid & 3, wn = wid >> 2;
    const uint32_t a_off = (uint32_t)((wm * 32 + (lane & 15)) * 80 + (lane >> 4) * 16);
    const uint32_t b_off = (uint32_t)((lane & 15) * 272 + (lane >> 4) * 16);

    float acc[2][8][4];
#pragma unroll
    for (int mt = 0; mt < 2; mt++)
#pragma unroll
        for (int nt = 0; nt < 8; nt++)
#pragma unroll
            for (int j = 0; j < 4; j++) acc[mt][nt][j] = 0.f;

#pragma unroll
    for (int s = 0; s < NSTG - 1; s++)
        if (s < nch) load_stage(s);

    int cur = 0;
    for (int i = 0; i < nch; i++) {
        // wait until stage `cur` is resident
        int rem_groups = nch - 1 - i;           // groups issued after stage i (if no more loads)
        if (i + NSTG - 1 < nch) cp_wait<NSTG - 2>();
        else if (rem_groups >= NSTG - 2) cp_wait<NSTG - 2>();
        else if (NSTG >= 4 && rem_groups == 2) cp_wait<2>();
        else if (rem_groups == 1) cp_wait<1>();
        else cp_wait<0>();
        __syncthreads();   // also protects stage (cur-1): all warps done reading it
        if (i + NSTG - 1 < nch) {
            int ns = cur + NSTG - 1;
            if (ns >= NSTG) ns -= NSTG;
            load_stage(ns);
        }

        uint32_t sbase = smb + cur * stageB;
#pragma unroll
        for (int ks = 0; ks < 2; ks++) {
            uint32_t aF[NP][2][4];
#pragma unroll
            for (int p = 0; p < NP; p++)
#pragma unroll
                for (int mt = 0; mt < 2; mt++)
                    ldsm4(aF[p][mt], sbase + p * PT_A + mt * 16 * 80 + ks * 32 + a_off);
#pragma unroll
            for (int ib = 0; ib < NP; ib++) {
                uint32_t bF[8][2];
#pragma unroll
                for (int q = 0; q < 4; q++) {
                    uint32_t r4[4];
                    ldsm4t(r4, sbase + NP * PT_A + ib * PT_B + ks * 4352
                               + (uint32_t)((wn * 64 + q * 16) * 2) + b_off);
                    bF[q*2][0] = r4[0]; bF[q*2][1] = r4[1];
                    bF[q*2+1][0] = r4[2]; bF[q*2+1][1] = r4[3];
                }
#pragma unroll
                for (int ia = 0; ia < NP; ia++) {
                    if (ia + ib >= NP) continue;
#pragma unroll
                    for (int mt = 0; mt < 2; mt++)
#pragma unroll
                        for (int nt = 0; nt < 8; nt++)
                            mma_bf16(acc[mt][nt], aF[ia][mt], bF[nt]);
                }
            }
        }
        cur++; if (cur == NSTG) cur = 0;
    }

    // ---- epilogue ----
    __syncthreads();
    float* ep = (float*)sm;
#pragma unroll
    for (int mt = 0; mt < 2; mt++) {
        int r0 = wm * 32 + mt * 16 + (lane >> 2);
#pragma unroll
        for (int nt = 0; nt < 8; nt++) {
            int col = wn * 64 + nt * 8 + (lane & 3) * 2;
            ep[r0 * 132 + col]       = acc[mt][nt][0];
            ep[r0 * 132 + col + 1]   = acc[mt][nt][1];
            ep[(r0+8) * 132 + col]   = acc[mt][nt][2];
            ep[(r0+8) * 132 + col+1] = acc[mt][nt][3];
        }
    }
    __syncthreads();

    {
        int r = tid >> 1, half = tid & 1;
        ll row = (ll)z * MrowsPerZ + m0 + r;
        int cbase = half * 64;
        const float* bb = bias + (ll)z * biasPerZ + n0 + cbase;
#pragma unroll
        for (int q = 0; q < 8; q++) {
            float v[8];
#pragma unroll
            for (int j = 0; j < 8; j++)
                v[j] = ep[r * 132 + cbase + q * 8 + j] + bb[q * 8 + j];
            if (OUTMODE == 0) {
                float* o = (float*)outp + row * (ll)HH / (HH/N) + 0; // placeholder avoided below
                (void)o;
            }
            if (OUTMODE == 0) {
                float* o2 = (float*)outp + row * (ll)N + n0 + cbase + q * 8;
                float4 o0 = {v[0], v[1], v[2], v[3]};
                float4 o1 = {v[4], v[5], v[6], v[7]};
                ((float4*)o2)[0] = o0; ((float4*)o2)[1] = o1;
            } else {
                __align__(16) uint16_t hs[8], ms[8], ls[8];
#pragma unroll
                for (int j = 0; j < 8; j++) {
                    float vv = fmaxf(v[j], 0.f);
                    split3v(vv, hs + j, ms + j, ls + j);
                }
                bf16* o0 = (bf16*)outp + row * (ll)N + n0 + cbase + q * 8;
                *(uint4*)o0 = *(uint4*)hs;
                *(uint4*)(o0 + OpS) = *(uint4*)ms;
                if (OUTMODE == 1) *(uint4*)(o0 + 2 * OpS) = *(uint4*)ls;
            }
        }
    }
}

// ---------------- router: logits from NPL planes, softmax, top-2 ----------------
template<int NPL>
__device__ __forceinline__ void router_logits_warp(const bf16* r0, ll ps, const float* Wr3,
                                                   int lane, float* acc)
{
#pragma unroll
    for (int e = 0; e < EE; e++) acc[e] = 0.f;
    for (int k = lane * 4; k < HH; k += 128) {
        float vv[4];
#pragma unroll
        for (int h = 0; h < 2; h++) {
            __nv_bfloat162 a = *(const __nv_bfloat162*)(r0 + k + 2 * h);
            __nv_bfloat162 b = *(const __nv_bfloat162*)(r0 + ps + k + 2 * h);
            float sx = __bfloat162float(a.x) + __bfloat162float(b.x);
            float sy = __bfloat162float(a.y) + __bfloat162float(b.y);
            if (NPL == 3) {
                __nv_bfloat162 c = *(const __nv_bfloat162*)(r0 + 2 * ps + k + 2 * h);
                sx += __bfloat162float(c.x); sy += __bfloat162float(c.y);
            }
            vv[2*h+0] = sx; vv[2*h+1] = sy;
        }
#pragma unroll
        for (int j = 0; j < 4; j++) {
            const float* w = Wr3 + (ll)(k + j) * EE;
            float xv = vv[j];
#pragma unroll
            for (int e = 0; e < EE; e++) acc[e] += xv * w[e];
        }
    }
#pragma unroll
    for (int e = 0; e < EE; e++)
#pragma unroll
        for (int off = 16; off > 0; off >>= 1)
            acc[e] += __shfl_xor_sync(0xFFFFFFFFu, acc[e], off);
}

__device__ __forceinline__ void topk_write(const float* accv, const float* br3,
                                           float* tp, int* te, int tok,
                                           int* fix_tok, int* fix_cnt)
{
    float lg[EE], mx = -1e30f;
#pragma unroll
    for (int e = 0; e < EE; e++) { lg[e] = accv[e] + br3[e]; mx = fmaxf(mx, lg[e]); }
    float p[EE], s = 0.f;
#pragma unroll
    for (int e = 0; e < EE; e++) { p[e] = __expf(lg[e] - mx); s += p[e]; }
    float inv = 1.f / s;
    int i0 = 0;
#pragma unroll
    for (int e = 1; e < EE; e++) if (lg[e] > lg[i0]) i0 = e;
    int i1 = (i0 == 0) ? 1 : 0;
#pragma unroll
    for (int e = 0; e < EE; e++) if (e != i0 && lg[e] > lg[i1]) i1 = e;
    if (fix_tok) {
        float l3 = -1e30f;
#pragma unroll
        for (int e = 0; e < EE; e++) if (e != i0 && e != i1) l3 = fmaxf(l3, lg[e]);
        if (lg[i1] - l3 < FIX_THRESH) {
            int ix = atomicAdd(fix_cnt, 1);
            if (ix < FIXCAP) fix_tok[ix] = tok;
        }
    }
    tp[tok * 2 + 0] = p[i0] * inv;
    tp[tok * 2 + 1] = p[i1] * inv;
    te[tok * 2 + 0] = i0;
    te[tok * 2 + 1] = i1;
}

__global__ __launch_bounds__(128)
void router_topk2_kernel(const bf16* __restrict__ h2s, ll ps,
                         const float* __restrict__ Wr3, const float* __restrict__ br3,
                         float* __restrict__ tp, int* __restrict__ te,
                         int* __restrict__ fix_tok, int* __restrict__ fix_cnt)
{
    int tok = (blockIdx.x * blockDim.x + threadIdx.x) >> 5;
    int lane = threadIdx.x & 31;
    if (tok >= BT) return;
    float acc[EE];
    router_logits_warp<2>(h2s + (ll)tok * HH, ps, Wr3, lane, acc);
    if (lane == 0) topk_write(acc, br3, tp, te, tok, fix_tok, fix_cnt);
}

__global__ __launch_bounds__(128)
void router_fix_kernel(const bf16* __restrict__ h2f, ll ps,
                       const float* __restrict__ Wr3, const float* __restrict__ br3,
                       const int* __restrict__ fix_tok,
                       float* __restrict__ tp, int* __restrict__ te)
{
    int r = (blockIdx.x * blockDim.x + threadIdx.x) >> 5;
    int lane = threadIdx.x & 31;
    if (r >= FIXCAP) return;
    int tok = fix_tok[r];
    if (tok < 0) return;
    float acc[EE];
    router_logits_warp<3>(h2f + (ll)r * HH, ps, Wr3, lane, acc);
    if (lane == 0) topk_write(acc, br3, tp, te, tok, nullptr, nullptr);
}

__global__ void init_fix_kernel(int* fix_tok, int* fix_cnt, int* slot_tok) {
    int i = blockIdx.x * 256 + threadIdx.x;
    if (i < FIXCAP) fix_tok[i] = -1;
    if (i == 0) *fix_cnt = 0;
    if (i < NSLOT) slot_tok[i] = -1;
}

__global__ __launch_bounds__(256)
void route_scan_kernel(const int* __restrict__ te, int* __restrict__ dest, int* __restrict__ slot_tok)
{
    __shared__ int se[TT * KTOP];
    int b = blockIdx.x;
    for (int i = threadIdx.x; i < TT * KTOP; i += 256) se[i] = te[b * TT * KTOP + i];
    __syncthreads();
    if (threadIdx.x < EE) {
        int e = threadIdx.x, cnt = 0;
        for (int i = 0; i < TT * KTOP; i++) {
            if (se[i] == e) {
                int gi = b * TT * KTOP + i;
                if (cnt < CAPQ) {
                    int s = e * (BB * CAPQ) + b * CAPQ + cnt;
                    dest[gi] = s;
                    slot_tok[s] = b * TT + (i >> 1);
                } else dest[gi] = -1;
                cnt++;
            }
        }
    }
}

__global__ __launch_bounds__(256)
void combine_kernel(const float* __restrict__ ey, const float* __restrict__ topk_p,
                    const int* __restrict__ dest, float* __restrict__ out)
{
    int tok = blockIdx.x;
    int c = threadIdx.x * 4;
    float4 r = make_float4(0.f, 0.f, 0.f, 0.f);
#pragma unroll
    for (int k = 0; k < KTOP; k++) {
        int s = dest[tok * 2 + k];
        if (s >= 0) {
            float p = topk_p[tok * 2 + k];
            float4 v = *(const float4*)(ey + (ll)s * CC + c);
            r.x += p * v.x; r.y += p * v.y; r.z += p * v.z; r.w += p * v.w;
        }
    }
    *(float4*)(out + (ll)tok * CC + c) = r;
}

// ---------------- launch ----------------
extern "C" void kernel_launch(void* const* d_in, const int* in_sizes, int n_in,
                              void* d_out, int out_size)
{
    (void)in_sizes; (void)n_in; (void)out_size;
    const float* x   = (const float*)d_in[0];
    const float* Wr1 = (const float*)d_in[1];
    const float* br1 = (const float*)d_in[2];
    const float* Wr2 = (const float*)d_in[3];
    const float* br2 = (const float*)d_in[4];
    const float* Wr3 = (const float*)d_in[5];
    const float* br3 = (const float*)d_in[6];
    const float* We1 = (const float*)d_in[7];
    const float* be1 = (const float*)d_in[8];
    const float* We2 = (const float*)d_in[9];
    const float* be2 = (const float*)d_in[10];
    float* out = (float*)d_out;

    bf16 *xs, *wr1t, *wr2t, *we1t, *we2t, *h1s, *h2s, *h1f, *h2f, *ehs;
    float *ey, *tp; int *te, *dest, *stok, *ftok, *fcnt;
    cudaGetSymbolAddress((void**)&xs,   g_xs);
    cudaGetSymbolAddress((void**)&wr1t, g_wr1t);
    cudaGetSymbolAddress((void**)&wr2t, g_wr2t);
    cudaGetSymbolAddress((void**)&we1t, g_we1t);
    cudaGetSymbolAddress((void**)&we2t, g_we2t);
    cudaGetSymbolAddress((void**)&h1s,  g_h1s);
    cudaGetSymbolAddress((void**)&h2s,  g_h2s);
    cudaGetSymbolAddress((void**)&h1f,  g_h1f);
    cudaGetSymbolAddress((void**)&h2f,  g_h2f);
    cudaGetSymbolAddress((void**)&ehs,  g_ehs);
    cudaGetSymbolAddress((void**)&ey,   g_ey);
    cudaGetSymbolAddress((void**)&tp,   g_topk_p);
    cudaGetSymbolAddress((void**)&te,   g_topk_e);
    cudaGetSymbolAddress((void**)&dest, g_dest);
    cudaGetSymbolAddress((void**)&stok, g_slot_tok);
    cudaGetSymbolAddress((void**)&ftok, g_fix_tok);
    cudaGetSymbolAddress((void**)&fcnt, g_fix_cnt);

    const int SM2 = 4 * 2 * (PT_A + PT_B);   // 151552 (NP=2, 4-stage)
    const int SM3 = 3 * 3 * (PT_A + PT_B);   // 170496 (NP=3, 3-stage)
    static int smem_set = 0;
    if (!smem_set) {
        cudaFuncSetAttribute(tc_gemm<2,2,4>, cudaFuncAttributeMaxDynamicSharedMemorySize, SM2);
        cudaFuncSetAttribute(tc_gemm<2,0,4>, cudaFuncAttributeMaxDynamicSharedMemorySize, SM2);
        cudaFuncSetAttribute(tc_gemm<3,1,3>, cudaFuncAttributeMaxDynamicSharedMemorySize, SM3);
        smem_set = 1;
    }

    // 0) elementwise splits + table init
    splitN_kernel<3><<<(ll)BT * CC / 1024, 256>>>(x,   xs,   (ll)BT * CC);
    splitN_kernel<3><<<(ll)CC * HH / 1024, 256>>>(Wr1, wr1t, (ll)CC * HH);
    splitN_kernel<3><<<(ll)HH * HH / 1024, 256>>>(Wr2, wr2t, (ll)HH * HH);
    splitN_kernel<2><<<(ll)EE * CC * HH / 1024, 256>>>(We1, we1t, (ll)EE * CC * HH);
    splitN_kernel<2><<<(ll)EE * HH * CC / 1024, 256>>>(We2, we2t, (ll)EE * HH * CC);
    init_fix_kernel<<<(NSLOT + 255) / 256, 256>>>(ftok, fcnt, stok);

    // 1) h1 = relu(x @ Wr1 + br1) : split2 out
    tc_gemm<2,2,4><<<dim3((BT/128)*(HH/128), 1), 256, SM2>>>(
        xs, (ll)BT*CC, BT, wr1t, (ll)CC*HH, br1, 0,
        h1s, (ll)BT*HH, BT, nullptr, 0, HH, CC, BT/128, HH/128);

    // 2) h2 = relu(h1 @ Wr2 + br2) : split2 out
    tc_gemm<2,2,4><<<dim3((BT/128)*(HH/128), 1), 256, SM2>>>(
        h1s, (ll)BT*HH, BT, wr2t, (ll)HH*HH, br2, 0,
        h2s, (ll)BT*HH, BT, nullptr, 0, HH, HH, BT/128, HH/128);

    // 3) logits -> softmax -> top-2, flag marginal tokens
    router_topk2_kernel<<<(BT * 32) / 128, 128>>>(h2s, (ll)BT*HH, Wr3, br3, tp, te, ftok, fcnt);

    // 3b) exact (split3) fixup chain for flagged tokens
    tc_gemm<3,1,3><<<dim3((FIXCAP/128)*(HH/128), 1), 256, SM3>>>(
        xs, (ll)BT*CC, FIXCAP, wr1t, (ll)CC*HH, br1, 0,
        h1f, (ll)FIXCAP*HH, FIXCAP, ftok, FIXCAP, HH, CC, FIXCAP/128, HH/128);
    tc_gemm<3,1,3><<<dim3((FIXCAP/128)*(HH/128), 1), 256, SM3>>>(
        h1f, (ll)FIXCAP*HH, FIXCAP, wr2t, (ll)HH*HH, br2, 0,
        h2f, (ll)FIXCAP*HH, FIXCAP, nullptr, 0, HH, HH, FIXCAP/128, HH/128);
    router_fix_kernel<<<(FIXCAP * 32) / 128, 128>>>(h2f, (ll)FIXCAP*HH, Wr3, br3, ftok, tp, te);

    // 4) routing tables
    route_scan_kernel<<<BB, 256>>>(te, dest, stok);

    // 5) eh[e] = relu(gather(x) @ We1[e] + be1[e]) : split2 out
    tc_gemm<2,2,4><<<dim3((ROWS_E/128)*(HH/128), EE), 256, SM2>>>(
        xs, (ll)BT*CC, ROWS_E, we1t, (ll)EE*CC*HH, be1, HH,
        ehs, (ll)EE*ROWS_E*HH, ROWS_E, stok, ROWS_E, HH, CC, ROWS_E/128, HH/128);

    // 6) ey[e] = eh[e] @ We2[e] + be2[e] : fp32 out
    tc_gemm<2,0,4><<<dim3((ROWS_E/128)*(CC/128), EE), 256, SM2>>>(
        ehs, (ll)EE*ROWS_E*HH, ROWS_E, we2t, (ll)EE*HH*CC, be2, CC,
        ey, 0, ROWS_E, nullptr, 0, CC, HH, ROWS_E/128, CC/128);

    // 7) combine
    combine_kernel<<<BT, 256>>>(ey, tp, dest, out);
}

// round 13
// speedup vs baseline: 1.7173x; 1.1531x over previous
#include <cuda_runtime.h>
#include <cuda_fp16.h>
#include <stdint.h>

#define BB   8
#define TT   2048
#define CC   1024
#define EE   8
#define KTOP 2
#define CAPQ 320
#define HH   4096
#define BT   (BB*TT)
#define NSLOT (EE*BB*CAPQ)
#define ROWS_E (BB*CAPQ)
#define FIXCAP 1024
#define FIX_THRESH 5e-3f

typedef __half hf;
typedef long long ll;

// ---------------- scratch (all split-2 fp16 planes) ----------------
__device__ hf    g_xs  [2ll*BT*CC];
__device__ hf    g_wr1t[2ll*CC*HH];
__device__ hf    g_wr2t[2ll*HH*HH];
__device__ hf    g_we1t[2ll*EE*CC*HH];
__device__ hf    g_we2t[2ll*EE*HH*CC];
__device__ hf    g_h1s [2ll*BT*HH];
__device__ hf    g_h2s [2ll*BT*HH];
__device__ hf    g_h1f [2ll*FIXCAP*HH];
__device__ hf    g_h2f [2ll*FIXCAP*HH];
__device__ hf    g_ehs [2ll*EE*ROWS_E*HH];
__device__ float g_ey  [(ll)EE*ROWS_E*CC];
__device__ float g_topk_p[BT*KTOP];
__device__ int   g_topk_e[BT*KTOP];
__device__ int   g_dest[BT*KTOP];
__device__ int   g_slot_tok[NSLOT];
__device__ int   g_fix_tok[FIXCAP];
__device__ int   g_fix_cnt;

// ---------------- PTX helpers ----------------
__device__ __forceinline__ uint32_t smem_u32(const void* p) {
    uint32_t a;
    asm("{ .reg .u64 t; cvta.to.shared.u64 t, %1; cvt.u32.u64 %0, t; }" : "=r"(a) : "l"(p));
    return a;
}
__device__ __forceinline__ void cp16(uint32_t dst, const void* src, int ssz) {
    asm volatile("cp.async.cg.shared.global [%0], [%1], 16, %2;" :: "r"(dst), "l"(src), "r"(ssz));
}
__device__ __forceinline__ void cp_commit() { asm volatile("cp.async.commit_group;" ::: "memory"); }
template<int N> __device__ __forceinline__ void cp_wait() {
    asm volatile("cp.async.wait_group %0;" :: "n"(N) : "memory");
}
__device__ __forceinline__ void ldsm4(uint32_t* r, uint32_t addr) {
    asm volatile("ldmatrix.sync.aligned.m8n8.x4.shared.b16 {%0,%1,%2,%3}, [%4];"
        : "=r"(r[0]), "=r"(r[1]), "=r"(r[2]), "=r"(r[3]) : "r"(addr));
}
__device__ __forceinline__ void ldsm4t(uint32_t* r, uint32_t addr) {
    asm volatile("ldmatrix.sync.aligned.m8n8.x4.trans.shared.b16 {%0,%1,%2,%3}, [%4];"
        : "=r"(r[0]), "=r"(r[1]), "=r"(r[2]), "=r"(r[3]) : "r"(addr));
}
__device__ __forceinline__ void mma_f16(float* c, const uint32_t* a, const uint32_t* b) {
    asm volatile("mma.sync.aligned.m16n8k16.row.col.f32.f16.f16.f32 "
        "{%0,%1,%2,%3}, {%4,%5,%6,%7}, {%8,%9}, {%0,%1,%2,%3};"
        : "+f"(c[0]), "+f"(c[1]), "+f"(c[2]), "+f"(c[3])
        : "r"(a[0]), "r"(a[1]), "r"(a[2]), "r"(a[3]), "r"(b[0]), "r"(b[1]));
}

// ---------------- fp16 split-2 helpers ----------------
__device__ __forceinline__ void split2v(float v, uint16_t* h, uint16_t* m) {
    __half hb = __float2half_rn(v);
    __half mb = __float2half_rn(v - __half2float(hb));
    *h = *(uint16_t*)&hb; *m = *(uint16_t*)&mb;
}

__global__ __launch_bounds__(256)
void split2_kernel(const float* __restrict__ in, hf* __restrict__ out, ll ps) {
    ll i = ((ll)blockIdx.x * 256 + threadIdx.x) * 4;
    float4 v = *(const float4*)(in + i);
    uint16_t h[4], m[4];
    split2v(v.x, h+0, m+0); split2v(v.y, h+1, m+1);
    split2v(v.z, h+2, m+2); split2v(v.w, h+3, m+3);
    *(uint2*)(out + i)      = *(uint2*)h;
    *(uint2*)(out + ps + i) = *(uint2*)m;
}

// ---------------- split-fp16 GEMM via mma.sync ----------------
// C = act( sum_{ia+ib<2, ib<NPB} A_plane[ia] @ B_plane[ib] + bias )
// NPB=1: 2 combos = fullA x fp16(B). NPB=2: 3 combos = ~exact (2^-22).
// Tile 128x128x32, 8 warps (4m x 2n), NSTG-stage cp.async ring, 1 barrier/chunk.
// OUTMODE: 0 = fp32 out; 1 = relu + split2 fp16 planes.
#define PT_A 10240   // 128 rows x 80B
#define PT_B 8704    // 32 rows x 272B
template<int NPB, int OUTMODE, int NSTG>
__global__ __launch_bounds__(256, 1)
void tc_gemm(const hf* __restrict__ A, ll ApS, int ArowsPerZ,
             const hf* __restrict__ B, ll BpS,
             const float* __restrict__ bias, int biasPerZ,
             void* __restrict__ outp, ll OpS, int MrowsPerZ,
             const int* __restrict__ gidx, int gstride,
             int N, int K, int gm, int gn)
{
    constexpr int stageB = 2 * PT_A + NPB * PT_B;
    constexpr int NA = 4;          // A cp16 units per thread (2 planes)
    constexpr int NB = 2 * NPB;    // B cp16 units per thread

    extern __shared__ char sm[];
    __shared__ int rowtok[128];
    const uint32_t smb = smem_u32(sm);
    const int tid = threadIdx.x;
    const int wid = tid >> 5, lane = tid & 31;
    const int z = blockIdx.y;

    int bid = blockIdx.x;
    int grp = bid / (gn * 8);
    int rem = bid - grp * gn * 8;
    int gsz = gm - grp * 8; if (gsz > 8) gsz = 8;
    int mtile = grp * 8 + rem % gsz;
    int ntile = rem / gsz;
    const int m0 = mtile << 7, n0 = ntile << 7;

    if (tid < 128)
        rowtok[tid] = gidx ? gidx[(ll)z * gstride + m0 + tid] : (z * ArowsPerZ + m0 + tid);
    __syncthreads();

    const int nch = K >> 5;
    const ll KN = (ll)K * N;
    const ll bstep = (ll)N * 64;

    const char* srcA[NA]; uint32_t dstA[NA]; uint32_t amask = 0;
    const char* srcB[NB]; uint32_t dstB[NB];
#pragma unroll
    for (int j = 0; j < NA; j++) {
        int u = tid + j * 256;
        int p = u >> 9, t = u & 511, r = t >> 2, c = t & 3;
        dstA[j] = (uint32_t)(p * PT_A + r * 80 + c * 16);
        int ra = rowtok[r];
        if (ra < 0) srcA[j] = (const char*)A;
        else { srcA[j] = (const char*)(A + (ll)p * ApS + (ll)ra * K + c * 8); amask |= 1u << j; }
    }
#pragma unroll
    for (int j = 0; j < NB; j++) {
        int u = tid + j * 256;
        int p = u >> 9, t = u & 511, r = t >> 4, c = t & 15;
        dstB[j] = (uint32_t)(2 * PT_A + p * PT_B + r * 272 + c * 16);
        srcB[j] = (const char*)(B + (ll)p * BpS + (ll)z * KN + (ll)r * N + n0 + c * 8);
    }

    auto load_stage = [&](int s) {
        uint32_t sb = smb + s * stageB;
#pragma unroll
        for (int j = 0; j < NA; j++) {
            cp16(sb + dstA[j], srcA[j], (amask >> j & 1) ? 16 : 0);
            srcA[j] += 64;
        }
#pragma unroll
        for (int j = 0; j < NB; j++) {
            cp16(sb + dstB[j], srcB[j], 16);
            srcB[j] += bstep;
        }
        cp_commit();
    };

    const int wm = wid & 3, wn = wid >> 2;
    const uint32_t a_off = (uint32_t)((wm * 32 + (lane & 15)) * 80 + (lane >> 4) * 16);
    const uint32_t b_off = (uint32_t)((lane & 15) * 272 + (lane >> 4) * 16);

    float acc[2][8][4];
#pragma unroll
    for (int mt = 0; mt < 2; mt++)
#pragma unroll
        for (int nt = 0; nt < 8; nt++)
#pragma unroll
            for (int j = 0; j < 4; j++) acc[mt][nt][j] = 0.f;

#pragma unroll
    for (int s = 0; s < NSTG - 1; s++)
        if (s < nch) load_stage(s);

    int cur = 0;
    for (int i = 0; i < nch; i++) {
        int rem_groups = nch - 1 - i;
        if (i + NSTG - 1 < nch) cp_wait<NSTG - 2>();
        else if (rem_groups >= NSTG - 2) cp_wait<NSTG - 2>();
        else if (NSTG >= 4 && rem_groups == 2) cp_wait<2>();
        else if (rem_groups == 1) cp_wait<1>();
        else cp_wait<0>();
        __syncthreads();
        if (i + NSTG - 1 < nch) {
            int ns = cur + NSTG - 1;
            if (ns >= NSTG) ns -= NSTG;
            load_stage(ns);
        }

        uint32_t sbase = smb + cur * stageB;
#pragma unroll
        for (int ks = 0; ks < 2; ks++) {
            uint32_t aF[2][2][4];
#pragma unroll
            for (int p = 0; p < 2; p++)
#pragma unroll
                for (int mt = 0; mt < 2; mt++)
                    ldsm4(aF[p][mt], sbase + p * PT_A + mt * 16 * 80 + ks * 32 + a_off);
#pragma unroll
            for (int ib = 0; ib < NPB; ib++) {
                uint32_t bF[8][2];
#pragma unroll
                for (int q = 0; q < 4; q++) {
                    uint32_t r4[4];
                    ldsm4t(r4, sbase + 2 * PT_A + ib * PT_B + ks * 4352
                               + (uint32_t)((wn * 64 + q * 16) * 2) + b_off);
                    bF[q*2][0] = r4[0]; bF[q*2][1] = r4[1];
                    bF[q*2+1][0] = r4[2]; bF[q*2+1][1] = r4[3];
                }
#pragma unroll
                for (int ia = 0; ia < 2; ia++) {
                    if (ia + ib >= 2) continue;
#pragma unroll
                    for (int mt = 0; mt < 2; mt++)
#pragma unroll
                        for (int nt = 0; nt < 8; nt++)
                            mma_f16(acc[mt][nt], aF[ia][mt], bF[nt]);
                }
            }
        }
        cur++; if (cur == NSTG) cur = 0;
    }

    // ---- epilogue: stage fp32 tile in SMEM, coalesced bias/relu/split stores ----
    __syncthreads();
    float* ep = (float*)sm;
#pragma unroll
    for (int mt = 0; mt < 2; mt++) {
        int r0 = wm * 32 + mt * 16 + (lane >> 2);
#pragma unroll
        for (int nt = 0; nt < 8; nt++) {
            int col = wn * 64 + nt * 8 + (lane & 3) * 2;
            ep[r0 * 132 + col]       = acc[mt][nt][0];
            ep[r0 * 132 + col + 1]   = acc[mt][nt][1];
            ep[(r0+8) * 132 + col]   = acc[mt][nt][2];
            ep[(r0+8) * 132 + col+1] = acc[mt][nt][3];
        }
    }
    __syncthreads();

    {
        int r = tid >> 1, half = tid & 1;
        ll row = (ll)z * MrowsPerZ + m0 + r;
        int cbase = half * 64;
        const float* bb = bias + (ll)z * biasPerZ + n0 + cbase;
#pragma unroll
        for (int q = 0; q < 8; q++) {
            float v[8];
#pragma unroll
            for (int j = 0; j < 8; j++)
                v[j] = ep[r * 132 + cbase + q * 8 + j] + bb[q * 8 + j];
            if (OUTMODE == 0) {
                float* o = (float*)outp + row * (ll)N + n0 + cbase + q * 8;
                float4 o0 = {v[0], v[1], v[2], v[3]};
                float4 o1 = {v[4], v[5], v[6], v[7]};
                ((float4*)o)[0] = o0; ((float4*)o)[1] = o1;
            } else {
                __align__(16) uint16_t hs[8], ms[8];
#pragma unroll
                for (int j = 0; j < 8; j++) {
                    float vv = fmaxf(v[j], 0.f);
                    split2v(vv, hs + j, ms + j);
                }
                hf* o0 = (hf*)outp + row * (ll)N + n0 + cbase + q * 8;
                *(uint4*)o0 = *(uint4*)hs;
                *(uint4*)(o0 + OpS) = *(uint4*)ms;
            }
        }
    }
}

// ---------------- router: logits from 2 fp16 planes, softmax, top-2 ----------------
__device__ __forceinline__ void router_logits_warp(const hf* r0, ll ps, const float* Wr3,
                                                   int lane, float* acc)
{
#pragma unroll
    for (int e = 0; e < EE; e++) acc[e] = 0.f;
    for (int k = lane * 4; k < HH; k += 128) {
        float vv[4];
#pragma unroll
        for (int h = 0; h < 2; h++) {
            __half2 a = *(const __half2*)(r0 + k + 2 * h);
            __half2 b = *(const __half2*)(r0 + ps + k + 2 * h);
            float2 fa = __half22float2(a), fb = __half22float2(b);
            vv[2*h+0] = fa.x + fb.x;
            vv[2*h+1] = fa.y + fb.y;
        }
#pragma unroll
        for (int j = 0; j < 4; j++) {
            const float* w = Wr3 + (ll)(k + j) * EE;
            float xv = vv[j];
#pragma unroll
            for (int e = 0; e < EE; e++) acc[e] += xv * w[e];
        }
    }
#pragma unroll
    for (int e = 0; e < EE; e++)
#pragma unroll
        for (int off = 16; off > 0; off >>= 1)
            acc[e] += __shfl_xor_sync(0xFFFFFFFFu, acc[e], off);
}

__device__ __forceinline__ void topk_write(const float* accv, const float* br3,
                                           float* tp, int* te, int tok,
                                           int* fix_tok, int* fix_cnt)
{
    float lg[EE], mx = -1e30f;
#pragma unroll
    for (int e = 0; e < EE; e++) { lg[e] = accv[e] + br3[e]; mx = fmaxf(mx, lg[e]); }
    float p[EE], s = 0.f;
#pragma unroll
    for (int e = 0; e < EE; e++) { p[e] = __expf(lg[e] - mx); s += p[e]; }
    float inv = 1.f / s;
    int i0 = 0;
#pragma unroll
    for (int e = 1; e < EE; e++) if (lg[e] > lg[i0]) i0 = e;
    int i1 = (i0 == 0) ? 1 : 0;
#pragma unroll
    for (int e = 0; e < EE; e++) if (e != i0 && lg[e] > lg[i1]) i1 = e;
    if (fix_tok) {
        float l3 = -1e30f;
#pragma unroll
        for (int e = 0; e < EE; e++) if (e != i0 && e != i1) l3 = fmaxf(l3, lg[e]);
        if (lg[i1] - l3 < FIX_THRESH) {
            int ix = atomicAdd(fix_cnt, 1);
            if (ix < FIXCAP) fix_tok[ix] = tok;
        }
    }
    tp[tok * 2 + 0] = p[i0] * inv;
    tp[tok * 2 + 1] = p[i1] * inv;
    te[tok * 2 + 0] = i0;
    te[tok * 2 + 1] = i1;
}

__global__ __launch_bounds__(128)
void router_topk2_kernel(const hf* __restrict__ h2s, ll ps,
                         const float* __restrict__ Wr3, const float* __restrict__ br3,
                         float* __restrict__ tp, int* __restrict__ te,
                         int* __restrict__ fix_tok, int* __restrict__ fix_cnt)
{
    int tok = (blockIdx.x * blockDim.x + threadIdx.x) >> 5;
    int lane = threadIdx.x & 31;
    if (tok >= BT) return;
    float acc[EE];
    router_logits_warp(h2s + (ll)tok * HH, ps, Wr3, lane, acc);
    if (lane == 0) topk_write(acc, br3, tp, te, tok, fix_tok, fix_cnt);
}

__global__ __launch_bounds__(128)
void router_fix_kernel(const hf* __restrict__ h2f, ll ps,
                       const float* __restrict__ Wr3, const float* __restrict__ br3,
                       const int* __restrict__ fix_tok,
                       float* __restrict__ tp, int* __restrict__ te)
{
    int r = (blockIdx.x * blockDim.x + threadIdx.x) >> 5;
    int lane = threadIdx.x & 31;
    if (r >= FIXCAP) return;
    int tok = fix_tok[r];
    if (tok < 0) return;
    float acc[EE];
    router_logits_warp(h2f + (ll)r * HH, ps, Wr3, lane, acc);
    if (lane == 0) topk_write(acc, br3, tp, te, tok, nullptr, nullptr);
}

__global__ void init_fix_kernel(int* fix_tok, int* fix_cnt, int* slot_tok) {
    int i = blockIdx.x * 256 + threadIdx.x;
    if (i < FIXCAP) fix_tok[i] = -1;
    if (i == 0) *fix_cnt = 0;
    if (i < NSLOT) slot_tok[i] = -1;
}

__global__ __launch_bounds__(256)
void route_scan_kernel(const int* __restrict__ te, int* __restrict__ dest, int* __restrict__ slot_tok)
{
    __shared__ int se[TT * KTOP];
    int b = blockIdx.x;
    for (int i = threadIdx.x; i < TT * KTOP; i += 256) se[i] = te[b * TT * KTOP + i];
    __syncthreads();
    if (threadIdx.x < EE) {
        int e = threadIdx.x, cnt = 0;
        for (int i = 0; i < TT * KTOP; i++) {
            if (se[i] == e) {
                int gi = b * TT * KTOP + i;
                if (cnt < CAPQ) {
                    int s = e * (BB * CAPQ) + b * CAPQ + cnt;
                    dest[gi] = s;
                    slot_tok[s] = b * TT + (i >> 1);
                } else dest[gi] = -1;
                cnt++;
            }
        }
    }
}

__global__ __launch_bounds__(256)
void combine_kernel(const float* __restrict__ ey, const float* __restrict__ topk_p,
                    const int* __restrict__ dest, float* __restrict__ out)
{
    int tok = blockIdx.x;
    int c = threadIdx.x * 4;
    float4 r = make_float4(0.f, 0.f, 0.f, 0.f);
#pragma unroll
    for (int k = 0; k < KTOP; k++) {
        int s = dest[tok * 2 + k];
        if (s >= 0) {
            float p = topk_p[tok * 2 + k];
            float4 v = *(const float4*)(ey + (ll)s * CC + c);
            r.x += p * v.x; r.y += p * v.y; r.z += p * v.z; r.w += p * v.w;
        }
    }
    *(float4*)(out + (ll)tok * CC + c) = r;
}

// ---------------- launch ----------------
extern "C" void kernel_launch(void* const* d_in, const int* in_sizes, int n_in,
                              void* d_out, int out_size)
{
    (void)in_sizes; (void)n_in; (void)out_size;
    const float* x   = (const float*)d_in[0];
    const float* Wr1 = (const float*)d_in[1];
    const float* br1 = (const float*)d_in[2];
    const float* Wr2 = (const float*)d_in[3];
    const float* br2 = (const float*)d_in[4];
    const float* Wr3 = (const float*)d_in[5];
    const float* br3 = (const float*)d_in[6];
    const float* We1 = (const float*)d_in[7];
    const float* be1 = (const float*)d_in[8];
    const float* We2 = (const float*)d_in[9];
    const float* be2 = (const float*)d_in[10];
    float* out = (float*)d_out;

    hf *xs, *wr1t, *wr2t, *we1t, *we2t, *h1s, *h2s, *h1f, *h2f, *ehs;
    float *ey, *tp; int *te, *dest, *stok, *ftok, *fcnt;
    cudaGetSymbolAddress((void**)&xs,   g_xs);
    cudaGetSymbolAddress((void**)&wr1t, g_wr1t);
    cudaGetSymbolAddress((void**)&wr2t, g_wr2t);
    cudaGetSymbolAddress((void**)&we1t, g_we1t);
    cudaGetSymbolAddress((void**)&we2t, g_we2t);
    cudaGetSymbolAddress((void**)&h1s,  g_h1s);
    cudaGetSymbolAddress((void**)&h2s,  g_h2s);
    cudaGetSymbolAddress((void**)&h1f,  g_h1f);
    cudaGetSymbolAddress((void**)&h2f,  g_h2f);
    cudaGetSymbolAddress((void**)&ehs,  g_ehs);
    cudaGetSymbolAddress((void**)&ey,   g_ey);
    cudaGetSymbolAddress((void**)&tp,   g_topk_p);
    cudaGetSymbolAddress((void**)&te,   g_topk_e);
    cudaGetSymbolAddress((void**)&dest, g_dest);
    cudaGetSymbolAddress((void**)&stok, g_slot_tok);
    cudaGetSymbolAddress((void**)&ftok, g_fix_tok);
    cudaGetSymbolAddress((void**)&fcnt, g_fix_cnt);

    const int SMB1 = 4 * (2 * PT_A + 1 * PT_B);   // 116736 (NPB=1, 4-stage)
    const int SMB2 = 4 * (2 * PT_A + 2 * PT_B);   // 151552 (NPB=2, 4-stage)
    static int smem_set = 0;
    if (!smem_set) {
        cudaFuncSetAttribute(tc_gemm<1,1,4>, cudaFuncAttributeMaxDynamicSharedMemorySize, SMB1);
        cudaFuncSetAttribute(tc_gemm<2,1,4>, cudaFuncAttributeMaxDynamicSharedMemorySize, SMB2);
        cudaFuncSetAttribute(tc_gemm<2,0,4>, cudaFuncAttributeMaxDynamicSharedMemorySize, SMB2);
        smem_set = 1;
    }

    // 0) fp16 split-2 of input + all weights; table init
    split2_kernel<<<(ll)BT * CC / 1024, 256>>>(x,   xs,   (ll)BT * CC);
    split2_kernel<<<(ll)CC * HH / 1024, 256>>>(Wr1, wr1t, (ll)CC * HH);
    split2_kernel<<<(ll)HH * HH / 1024, 256>>>(Wr2, wr2t, (ll)HH * HH);
    split2_kernel<<<(ll)EE * CC * HH / 1024, 256>>>(We1, we1t, (ll)EE * CC * HH);
    split2_kernel<<<(ll)EE * HH * CC / 1024, 256>>>(We2, we2t, (ll)EE * HH * CC);
    init_fix_kernel<<<(NSLOT + 255) / 256, 256>>>(ftok, fcnt, stok);

    // 1) h1 = relu(x @ Wr1 + br1) : 2-combo (fullA x fp16 B), split2 out
    tc_gemm<1,1,4><<<dim3((BT/128)*(HH/128), 1), 256, SMB1>>>(
        xs, (ll)BT*CC, BT, wr1t, (ll)CC*HH, br1, 0,
        h1s, (ll)BT*HH, BT, nullptr, 0, HH, CC, BT/128, HH/128);

    // 2) h2 = relu(h1 @ Wr2 + br2) : 2-combo, split2 out
    tc_gemm<1,1,4><<<dim3((BT/128)*(HH/128), 1), 256, SMB1>>>(
        h1s, (ll)BT*HH, BT, wr2t, (ll)HH*HH, br2, 0,
        h2s, (ll)BT*HH, BT, nullptr, 0, HH, HH, BT/128, HH/128);

    // 3) logits -> softmax -> top-2, flag marginal tokens (gap23 < 5e-3)
    router_topk2_kernel<<<(BT * 32) / 128, 128>>>(h2s, (ll)BT*HH, Wr3, br3, tp, te, ftok, fcnt);

    // 3b) near-exact (3-combo fp16-split2, err ~2^-22) fixup chain for flagged tokens
    tc_gemm<2,1,4><<<dim3((FIXCAP/128)*(HH/128), 1), 256, SMB2>>>(
        xs, (ll)BT*CC, FIXCAP, wr1t, (ll)CC*HH, br1, 0,
        h1f, (ll)FIXCAP*HH, FIXCAP, ftok, FIXCAP, HH, CC, FIXCAP/128, HH/128);
    tc_gemm<2,1,4><<<dim3((FIXCAP/128)*(HH/128), 1), 256, SMB2>>>(
        h1f, (ll)FIXCAP*HH, FIXCAP, wr2t, (ll)HH*HH, br2, 0,
        h2f, (ll)FIXCAP*HH, FIXCAP, nullptr, 0, HH, HH, FIXCAP/128, HH/128);
    router_fix_kernel<<<(FIXCAP * 32) / 128, 128>>>(h2f, (ll)FIXCAP*HH, Wr3, br3, ftok, tp, te);

    // 4) routing tables
    route_scan_kernel<<<BB, 256>>>(te, dest, stok);

    // 5) eh[e] = relu(gather(x) @ We1[e] + be1[e]) : 3-combo, split2 out
    tc_gemm<2,1,4><<<dim3((ROWS_E/128)*(HH/128), EE), 256, SMB2>>>(
        xs, (ll)BT*CC, ROWS_E, we1t, (ll)EE*CC*HH, be1, HH,
        ehs, (ll)EE*ROWS_E*HH, ROWS_E, stok, ROWS_E, HH, CC, ROWS_E/128, HH/128);

    // 6) ey[e] = eh[e] @ We2[e] + be2[e] : 3-combo, fp32 out
    tc_gemm<2,0,4><<<dim3((ROWS_E/128)*(CC/128), EE), 256, SMB2>>>(
        ehs, (ll)EE*ROWS_E*HH, ROWS_E, we2t, (ll)EE*HH*CC, be2, CC,
        ey, 0, ROWS_E, nullptr, 0, CC, HH, ROWS_E/128, CC/128);

    // 7) combine
    combine_kernel<<<BT, 256>>>(ey, tp, dest, out);
}

// round 15
// speedup vs baseline: 1.9123x; 1.1136x over previous
#include <cuda_runtime.h>
#include <cuda_fp16.h>
#include <stdint.h>

#define BB   8
#define TT   2048
#define CC   1024
#define EE   8
#define KTOP 2
#define CAPQ 320
#define HH   4096
#define BT   (BB*TT)
#define NSLOT (EE*BB*CAPQ)
#define ROWS_E (BB*CAPQ)
#define FIXCAP 512
#define FIX_THRESH 2.5e-3f

typedef __half hf;
typedef long long ll;

// ---------------- scratch ----------------
__device__ hf    g_xs  [2ll*BT*CC];        // x split2
__device__ hf    g_wr1t[2ll*CC*HH];        // router weights split2 (fixup needs mid)
__device__ hf    g_wr2t[2ll*HH*HH];
__device__ hf    g_we1t[(ll)EE*CC*HH];     // expert weights: hi plane only
__device__ hf    g_we2t[(ll)EE*HH*CC];
__device__ hf    g_h1s [2ll*BT*HH];
__device__ hf    g_h2s [2ll*BT*HH];
__device__ hf    g_h1f [2ll*FIXCAP*HH];
__device__ hf    g_h2f [2ll*FIXCAP*HH];
__device__ hf    g_ehs [2ll*EE*ROWS_E*HH];
__device__ float g_ey  [(ll)EE*ROWS_E*CC];
__device__ float g_topk_p[BT*KTOP];
__device__ int   g_topk_e[BT*KTOP];
__device__ int   g_dest[BT*KTOP];
__device__ int   g_slot_tok[NSLOT];
__device__ int   g_fix_tok[FIXCAP];
__device__ int   g_fix_cnt;

// ---------------- PTX helpers ----------------
__device__ __forceinline__ uint32_t smem_u32(const void* p) {
    uint32_t a;
    asm("{ .reg .u64 t; cvta.to.shared.u64 t, %1; cvt.u32.u64 %0, t; }" : "=r"(a) : "l"(p));
    return a;
}
__device__ __forceinline__ void cp16(uint32_t dst, const void* src, int ssz) {
    asm volatile("cp.async.cg.shared.global [%0], [%1], 16, %2;" :: "r"(dst), "l"(src), "r"(ssz));
}
__device__ __forceinline__ void cp_commit() { asm volatile("cp.async.commit_group;" ::: "memory"); }
template<int N> __device__ __forceinline__ void cp_wait() {
    asm volatile("cp.async.wait_group %0;" :: "n"(N) : "memory");
}
__device__ __forceinline__ void ldsm4(uint32_t* r, uint32_t addr) {
    asm volatile("ldmatrix.sync.aligned.m8n8.x4.shared.b16 {%0,%1,%2,%3}, [%4];"
        : "=r"(r[0]), "=r"(r[1]), "=r"(r[2]), "=r"(r[3]) : "r"(addr));
}
__device__ __forceinline__ void ldsm4t(uint32_t* r, uint32_t addr) {
    asm volatile("ldmatrix.sync.aligned.m8n8.x4.trans.shared.b16 {%0,%1,%2,%3}, [%4];"
        : "=r"(r[0]), "=r"(r[1]), "=r"(r[2]), "=r"(r[3]) : "r"(addr));
}
__device__ __forceinline__ void mma_f16(float* c, const uint32_t* a, const uint32_t* b) {
    asm volatile("mma.sync.aligned.m16n8k16.row.col.f32.f16.f16.f32 "
        "{%0,%1,%2,%3}, {%4,%5,%6,%7}, {%8,%9}, {%0,%1,%2,%3};"
        : "+f"(c[0]), "+f"(c[1]), "+f"(c[2]), "+f"(c[3])
        : "r"(a[0]), "r"(a[1]), "r"(a[2]), "r"(a[3]), "r"(b[0]), "r"(b[1]));
}

// ---------------- fp16 split helpers ----------------
__device__ __forceinline__ void split2v(float v, uint16_t* h, uint16_t* m) {
    __half hb = __float2half_rn(v);
    __half mb = __float2half_rn(v - __half2float(hb));
    *h = *(uint16_t*)&hb; *m = *(uint16_t*)&mb;
}

__global__ __launch_bounds__(256)
void split2_kernel(const float* __restrict__ in, hf* __restrict__ out, ll ps) {
    ll i = ((ll)blockIdx.x * 256 + threadIdx.x) * 4;
    float4 v = *(const float4*)(in + i);
    uint16_t h[4], m[4];
    split2v(v.x, h+0, m+0); split2v(v.y, h+1, m+1);
    split2v(v.z, h+2, m+2); split2v(v.w, h+3, m+3);
    *(uint2*)(out + i)      = *(uint2*)h;
    *(uint2*)(out + ps + i) = *(uint2*)m;
}

// convert-only (hi plane) for expert weights
__global__ __launch_bounds__(256)
void cvt_kernel(const float* __restrict__ in, hf* __restrict__ out) {
    ll i = ((ll)blockIdx.x * 256 + threadIdx.x) * 4;
    float4 v = *(const float4*)(in + i);
    __half2 lo = __floats2half2_rn(v.x, v.y);
    __half2 hi = __floats2half2_rn(v.z, v.w);
    uint2 pk = { *(uint32_t*)&lo, *(uint32_t*)&hi };
    *(uint2*)(out + i) = pk;
}

// ---------------- split-fp16 GEMM via mma.sync ----------------
// C = act( sum_{ia+ib<2, ib<NPB} A_plane[ia] @ B_plane[ib] + bias )
// NPB=1: 2 combos = (Ah+Am) x Bh. NPB=2: 3 combos = ~exact (2^-22).
// Tile 128x128x32, 8 warps (4m x 2n), NSTG-stage cp.async ring, 1 barrier/chunk.
// OUTMODE: 0 = fp32 out; 1 = relu + split2 fp16 planes.
#define PT_A 10240   // 128 rows x 80B
#define PT_B 8704    // 32 rows x 272B
template<int NPB, int OUTMODE, int NSTG>
__global__ __launch_bounds__(256, 1)
void tc_gemm(const hf* __restrict__ A, ll ApS, int ArowsPerZ,
             const hf* __restrict__ B, ll BpS,
             const float* __restrict__ bias, int biasPerZ,
             void* __restrict__ outp, ll OpS, int MrowsPerZ,
             const int* __restrict__ gidx, int gstride,
             int N, int K, int gm, int gn)
{
    constexpr int stageB = 2 * PT_A + NPB * PT_B;
    constexpr int NA = 4;
    constexpr int NB = 2 * NPB;

    extern __shared__ char sm[];
    __shared__ int rowtok[128];
    const uint32_t smb = smem_u32(sm);
    const int tid = threadIdx.x;
    const int wid = tid >> 5, lane = tid & 31;
    const int z = blockIdx.y;

    int bid = blockIdx.x;
    int grp = bid / (gn * 8);
    int rem = bid - grp * gn * 8;
    int gsz = gm - grp * 8; if (gsz > 8) gsz = 8;
    int mtile = grp * 8 + rem % gsz;
    int ntile = rem / gsz;
    const int m0 = mtile << 7, n0 = ntile << 7;

    if (tid < 128)
        rowtok[tid] = gidx ? gidx[(ll)z * gstride + m0 + tid] : (z * ArowsPerZ + m0 + tid);
    __syncthreads();

    const int nch = K >> 5;
    const ll KN = (ll)K * N;
    const ll bstep = (ll)N * 64;

    const char* srcA[NA]; uint32_t dstA[NA]; uint32_t amask = 0;
    const char* srcB[NB]; uint32_t dstB[NB];
#pragma unroll
    for (int j = 0; j < NA; j++) {
        int u = tid + j * 256;
        int p = u >> 9, t = u & 511, r = t >> 2, c = t & 3;
        dstA[j] = (uint32_t)(p * PT_A + r * 80 + c * 16);
        int ra = rowtok[r];
        if (ra < 0) srcA[j] = (const char*)A;
        else { srcA[j] = (const char*)(A + (ll)p * ApS + (ll)ra * K + c * 8); amask |= 1u << j; }
    }
#pragma unroll
    for (int j = 0; j < NB; j++) {
        int u = tid + j * 256;
        int p = u >> 9, t = u & 511, r = t >> 4, c = t & 15;
        dstB[j] = (uint32_t)(2 * PT_A + p * PT_B + r * 272 + c * 16);
        srcB[j] = (const char*)(B + (ll)p * BpS + (ll)z * KN + (ll)r * N + n0 + c * 8);
    }

    auto load_stage = [&](int s) {
        uint32_t sb = smb + s * stageB;
#pragma unroll
        for (int j = 0; j < NA; j++) {
            cp16(sb + dstA[j], srcA[j], (amask >> j & 1) ? 16 : 0);
            srcA[j] += 64;
        }
#pragma unroll
        for (int j = 0; j < NB; j++) {
            cp16(sb + dstB[j], srcB[j], 16);
            srcB[j] += bstep;
        }
        cp_commit();
    };

    const int wm = wid & 3, wn = wid >> 2;
    const uint32_t a_off = (uint32_t)((wm * 32 + (lane & 15)) * 80 + (lane >> 4) * 16);
    const uint32_t b_off = (uint32_t)((lane & 15) * 272 + (lane >> 4) * 16);

    float acc[2][8][4];
#pragma unroll
    for (int mt = 0; mt < 2; mt++)
#pragma unroll
        for (int nt = 0; nt < 8; nt++)
#pragma unroll
            for (int j = 0; j < 4; j++) acc[mt][nt][j] = 0.f;

#pragma unroll
    for (int s = 0; s < NSTG - 1; s++)
        if (s < nch) load_stage(s);

    int cur = 0;
    for (int i = 0; i < nch; i++) {
        int rem_groups = nch - 1 - i;
        if (i + NSTG - 1 < nch) cp_wait<NSTG - 2>();
        else if (rem_groups >= NSTG - 2) cp_wait<NSTG - 2>();
        else if (NSTG >= 4 && rem_groups == 2) cp_wait<2>();
        else if (rem_groups == 1) cp_wait<1>();
        else cp_wait<0>();
        __syncthreads();
        if (i + NSTG - 1 < nch) {
            int ns = cur + NSTG - 1;
            if (ns >= NSTG) ns -= NSTG;
            load_stage(ns);
        }

        uint32_t sbase = smb + cur * stageB;
#pragma unroll
        for (int ks = 0; ks < 2; ks++) {
            uint32_t aF[2][2][4];
#pragma unroll
            for (int p = 0; p < 2; p++)
#pragma unroll
                for (int mt = 0; mt < 2; mt++)
                    ldsm4(aF[p][mt], sbase + p * PT_A + mt * 16 * 80 + ks * 32 + a_off);
#pragma unroll
            for (int ib = 0; ib < NPB; ib++) {
                uint32_t bF[8][2];
#pragma unroll
                for (int q = 0; q < 4; q++) {
                    uint32_t r4[4];
                    ldsm4t(r4, sbase + 2 * PT_A + ib * PT_B + ks * 4352
                               + (uint32_t)((wn * 64 + q * 16) * 2) + b_off);
                    bF[q*2][0] = r4[0]; bF[q*2][1] = r4[1];
                    bF[q*2+1][0] = r4[2]; bF[q*2+1][1] = r4[3];
                }
#pragma unroll
                for (int ia = 0; ia < 2; ia++) {
                    if (ia + ib >= 2) continue;
#pragma unroll
                    for (int mt = 0; mt < 2; mt++)
#pragma unroll
                        for (int nt = 0; nt < 8; nt++)
                            mma_f16(acc[mt][nt], aF[ia][mt], bF[nt]);
                }
            }
        }
        cur++; if (cur == NSTG) cur = 0;
    }

    // ---- epilogue ----
    __syncthreads();
    float* ep = (float*)sm;
#pragma unroll
    for (int mt = 0; mt < 2; mt++) {
        int r0 = wm * 32 + mt * 16 + (lane >> 2);
#pragma unroll
        for (int nt = 0; nt < 8; nt++) {
            int col = wn * 64 + nt * 8 + (lane & 3) * 2;
            ep[r0 * 132 + col]       = acc[mt][nt][0];
            ep[r0 * 132 + col + 1]   = acc[mt][nt][1];
            ep[(r0+8) * 132 + col]   = acc[mt][nt][2];
            ep[(r0+8) * 132 + col+1] = acc[mt][nt][3];
        }
    }
    __syncthreads();

    {
        int r = tid >> 1, half = tid & 1;
        ll row = (ll)z * MrowsPerZ + m0 + r;
        int cbase = half * 64;
        const float* bb = bias + (ll)z * biasPerZ + n0 + cbase;
#pragma unroll
        for (int q = 0; q < 8; q++) {
            float v[8];
#pragma unroll
            for (int j = 0; j < 8; j++)
                v[j] = ep[r * 132 + cbase + q * 8 + j] + bb[q * 8 + j];
            if (OUTMODE == 0) {
                float* o = (float*)outp + row * (ll)N + n0 + cbase + q * 8;
                float4 o0 = {v[0], v[1], v[2], v[3]};
                float4 o1 = {v[4], v[5], v[6], v[7]};
                ((float4*)o)[0] = o0; ((float4*)o)[1] = o1;
            } else {
                __align__(16) uint16_t hs[8], ms[8];
#pragma unroll
                for (int j = 0; j < 8; j++) {
                    float vv = fmaxf(v[j], 0.f);
                    split2v(vv, hs + j, ms + j);
                }
                hf* o0 = (hf*)outp + row * (ll)N + n0 + cbase + q * 8;
                *(uint4*)o0 = *(uint4*)hs;
                *(uint4*)(o0 + OpS) = *(uint4*)ms;
            }
        }
    }
}

// ---------------- router: logits from 2 fp16 planes, softmax, top-2 ----------------
__device__ __forceinline__ void router_logits_warp(const hf* r0, ll ps, const float* Wr3,
                                                   int lane, float* acc)
{
#pragma unroll
    for (int e = 0; e < EE; e++) acc[e] = 0.f;
    for (int k = lane * 4; k < HH; k += 128) {
        float vv[4];
#pragma unroll
        for (int h = 0; h < 2; h++) {
            __half2 a = *(const __half2*)(r0 + k + 2 * h);
            __half2 b = *(const __half2*)(r0 + ps + k + 2 * h);
            float2 fa = __half22float2(a), fb = __half22float2(b);
            vv[2*h+0] = fa.x + fb.x;
            vv[2*h+1] = fa.y + fb.y;
        }
#pragma unroll
        for (int j = 0; j < 4; j++) {
            const float* w = Wr3 + (ll)(k + j) * EE;
            float xv = vv[j];
#pragma unroll
            for (int e = 0; e < EE; e++) acc[e] += xv * w[e];
        }
    }
#pragma unroll
    for (int e = 0; e < EE; e++)
#pragma unroll
        for (int off = 16; off > 0; off >>= 1)
            acc[e] += __shfl_xor_sync(0xFFFFFFFFu, acc[e], off);
}

__device__ __forceinline__ void topk_write(const float* accv, const float* br3,
                                           float* tp, int* te, int tok,
                                           int* fix_tok, int* fix_cnt)
{
    float lg[EE], mx = -1e30f;
#pragma unroll
    for (int e = 0; e < EE; e++) { lg[e] = accv[e] + br3[e]; mx = fmaxf(mx, lg[e]); }
    float p[EE], s = 0.f;
#pragma unroll
    for (int e = 0; e < EE; e++) { p[e] = __expf(lg[e] - mx); s += p[e]; }
    float inv = 1.f / s;
    int i0 = 0;
#pragma unroll
    for (int e = 1; e < EE; e++) if (lg[e] > lg[i0]) i0 = e;
    int i1 = (i0 == 0) ? 1 : 0;
#pragma unroll
    for (int e = 0; e < EE; e++) if (e != i0 && lg[e] > lg[i1]) i1 = e;
    if (fix_tok) {
        float l3 = -1e30f;
#pragma unroll
        for (int e = 0; e < EE; e++) if (e != i0 && e != i1) l3 = fmaxf(l3, lg[e]);
        if (lg[i1] - l3 < FIX_THRESH) {
            int ix = atomicAdd(fix_cnt, 1);
            if (ix < FIXCAP) fix_tok[ix] = tok;
        }
    }
    tp[tok * 2 + 0] = p[i0] * inv;
    tp[tok * 2 + 1] = p[i1] * inv;
    te[tok * 2 + 0] = i0;
    te[tok * 2 + 1] = i1;
}

__global__ __launch_bounds__(128)
void router_topk2_kernel(const hf* __restrict__ h2s, ll ps,
                         const float* __restrict__ Wr3, const float* __restrict__ br3,
                         float* __restrict__ tp, int* __restrict__ te,
                         int* __restrict__ fix_tok, int* __restrict__ fix_cnt)
{
    int tok = (blockIdx.x * blockDim.x + threadIdx.x) >> 5;
    int lane = threadIdx.x & 31;
    if (tok >= BT) return;
    float acc[EE];
    router_logits_warp(h2s + (ll)tok * HH, ps, Wr3, lane, acc);
    if (lane == 0) topk_write(acc, br3, tp, te, tok, fix_tok, fix_cnt);
}

__global__ __launch_bounds__(128)
void router_fix_kernel(const hf* __restrict__ h2f, ll ps,
                       const float* __restrict__ Wr3, const float* __restrict__ br3,
                       const int* __restrict__ fix_tok,
                       float* __restrict__ tp, int* __restrict__ te)
{
    int r = (blockIdx.x * blockDim.x + threadIdx.x) >> 5;
    int lane = threadIdx.x & 31;
    if (r >= FIXCAP) return;
    int tok = fix_tok[r];
    if (tok < 0) return;
    float acc[EE];
    router_logits_warp(h2f + (ll)r * HH, ps, Wr3, lane, acc);
    if (lane == 0) topk_write(acc, br3, tp, te, tok, nullptr, nullptr);
}

__global__ void init_fix_kernel(int* fix_tok, int* fix_cnt, int* slot_tok) {
    int i = blockIdx.x * 256 + threadIdx.x;
    if (i < FIXCAP) fix_tok[i] = -1;
    if (i == 0) *fix_cnt = 0;
    if (i < NSLOT) slot_tok[i] = -1;
}

__global__ __launch_bounds__(256)
void route_scan_kernel(const int* __restrict__ te, int* __restrict__ dest, int* __restrict__ slot_tok)
{
    __shared__ int se[TT * KTOP];
    int b = blockIdx.x;
    for (int i = threadIdx.x; i < TT * KTOP; i += 256) se[i] = te[b * TT * KTOP + i];
    __syncthreads();
    if (threadIdx.x < EE) {
        int e = threadIdx.x, cnt = 0;
        for (int i = 0; i < TT * KTOP; i++) {
            if (se[i] == e) {
                int gi = b * TT * KTOP + i;
                if (cnt < CAPQ) {
                    int s = e * (BB * CAPQ) + b * CAPQ + cnt;
                    dest[gi] = s;
                    slot_tok[s] = b * TT + (i >> 1);
                } else dest[gi] = -1;
                cnt++;
            }
        }
    }
}

__global__ __launch_bounds__(256)
void combine_kernel(const float* __restrict__ ey, const float* __restrict__ topk_p,
                    const int* __restrict__ dest, float* __restrict__ out)
{
    int tok = blockIdx.x;
    int c = threadIdx.x * 4;
    float4 r = make_float4(0.f, 0.f, 0.f, 0.f);
#pragma unroll
    for (int k = 0; k < KTOP; k++) {
        int s = dest[tok * 2 + k];
        if (s >= 0) {
            float p = topk_p[tok * 2 + k];
            float4 v = *(const float4*)(ey + (ll)s * CC + c);
            r.x += p * v.x; r.y += p * v.y; r.z += p * v.z; r.w += p * v.w;
        }
    }
    *(float4*)(out + (ll)tok * CC + c) = r;
}

// ---------------- launch ----------------
extern "C" void kernel_launch(void* const* d_in, const int* in_sizes, int n_in,
                              void* d_out, int out_size)
{
    (void)in_sizes; (void)n_in; (void)out_size;
    const float* x   = (const float*)d_in[0];
    const float* Wr1 = (const float*)d_in[1];
    const float* br1 = (const float*)d_in[2];
    const float* Wr2 = (const float*)d_in[3];
    const float* br2 = (const float*)d_in[4];
    const float* Wr3 = (const float*)d_in[5];
    const float* br3 = (const float*)d_in[6];
    const float* We1 = (const float*)d_in[7];
    const float* be1 = (const float*)d_in[8];
    const float* We2 = (const float*)d_in[9];
    const float* be2 = (const float*)d_in[10];
    float* out = (float*)d_out;

    hf *xs, *wr1t, *wr2t, *we1t, *we2t, *h1s, *h2s, *h1f, *h2f, *ehs;
    float *ey, *tp; int *te, *dest, *stok, *ftok, *fcnt;
    cudaGetSymbolAddress((void**)&xs,   g_xs);
    cudaGetSymbolAddress((void**)&wr1t, g_wr1t);
    cudaGetSymbolAddress((void**)&wr2t, g_wr2t);
    cudaGetSymbolAddress((void**)&we1t, g_we1t);
    cudaGetSymbolAddress((void**)&we2t, g_we2t);
    cudaGetSymbolAddress((void**)&h1s,  g_h1s);
    cudaGetSymbolAddress((void**)&h2s,  g_h2s);
    cudaGetSymbolAddress((void**)&h1f,  g_h1f);
    cudaGetSymbolAddress((void**)&h2f,  g_h2f);
    cudaGetSymbolAddress((void**)&ehs,  g_ehs);
    cudaGetSymbolAddress((void**)&ey,   g_ey);
    cudaGetSymbolAddress((void**)&tp,   g_topk_p);
    cudaGetSymbolAddress((void**)&te,   g_topk_e);
    cudaGetSymbolAddress((void**)&dest, g_dest);
    cudaGetSymbolAddress((void**)&stok, g_slot_tok);
    cudaGetSymbolAddress((void**)&ftok, g_fix_tok);
    cudaGetSymbolAddress((void**)&fcnt, g_fix_cnt);

    const int SMB1 = 4 * (2 * PT_A + 1 * PT_B);   // 116736 (NPB=1, 4-stage)
    const int SMB2 = 4 * (2 * PT_A + 2 * PT_B);   // 151552 (NPB=2, 4-stage)
    static int smem_set = 0;
    if (!smem_set) {
        cudaFuncSetAttribute(tc_gemm<1,1,4>, cudaFuncAttributeMaxDynamicSharedMemorySize, SMB1);
        cudaFuncSetAttribute(tc_gemm<1,0,4>, cudaFuncAttributeMaxDynamicSharedMemorySize, SMB1);
        cudaFuncSetAttribute(tc_gemm<2,1,4>, cudaFuncAttributeMaxDynamicSharedMemorySize, SMB2);
        smem_set = 1;
    }

    // 0) prep: x + router weights split2; expert weights hi-plane convert; table init
    split2_kernel<<<(ll)BT * CC / 1024, 256>>>(x,   xs,   (ll)BT * CC);
    split2_kernel<<<(ll)CC * HH / 1024, 256>>>(Wr1, wr1t, (ll)CC * HH);
    split2_kernel<<<(ll)HH * HH / 1024, 256>>>(Wr2, wr2t, (ll)HH * HH);
    cvt_kernel<<<(ll)EE * CC * HH / 1024, 256>>>(We1, we1t);
    cvt_kernel<<<(ll)EE * HH * CC / 1024, 256>>>(We2, we2t);
    init_fix_kernel<<<(NSLOT + 255) / 256, 256>>>(ftok, fcnt, stok);

    // 1) h1 = relu(x @ Wr1 + br1) : 2-combo, split2 out
    tc_gemm<1,1,4><<<dim3((BT/128)*(HH/128), 1), 256, SMB1>>>(
        xs, (ll)BT*CC, BT, wr1t, (ll)CC*HH, br1, 0,
        h1s, (ll)BT*HH, BT, nullptr, 0, HH, CC, BT/128, HH/128);

    // 2) h2 = relu(h1 @ Wr2 + br2) : 2-combo, split2 out
    tc_gemm<1,1,4><<<dim3((BT/128)*(HH/128), 1), 256, SMB1>>>(
        h1s, (ll)BT*HH, BT, wr2t, (ll)HH*HH, br2, 0,
        h2s, (ll)BT*HH, BT, nullptr, 0, HH, HH, BT/128, HH/128);

    // 3) logits -> softmax -> top-2, flag marginal tokens (gap23 < 2.5e-3)
    router_topk2_kernel<<<(BT * 32) / 128, 128>>>(h2s, (ll)BT*HH, Wr3, br3, tp, te, ftok, fcnt);

    // 3b) near-exact (3-combo, err ~2^-22) fixup chain for flagged tokens
    tc_gemm<2,1,4><<<dim3((FIXCAP/128)*(HH/128), 1), 256, SMB2>>>(
        xs, (ll)BT*CC, FIXCAP, wr1t, (ll)CC*HH, br1, 0,
        h1f, (ll)FIXCAP*HH, FIXCAP, ftok, FIXCAP, HH, CC, FIXCAP/128, HH/128);
    tc_gemm<2,1,4><<<dim3((FIXCAP/128)*(HH/128), 1), 256, SMB2>>>(
        h1f, (ll)FIXCAP*HH, FIXCAP, wr2t, (ll)HH*HH, br2, 0,
        h2f, (ll)FIXCAP*HH, FIXCAP, nullptr, 0, HH, HH, FIXCAP/128, HH/128);
    router_fix_kernel<<<(FIXCAP * 32) / 128, 128>>>(h2f, (ll)FIXCAP*HH, Wr3, br3, ftok, tp, te);

    // 4) routing tables
    route_scan_kernel<<<BB, 256>>>(te, dest, stok);

    // 5) eh[e] = relu(gather(x) @ We1[e] + be1[e]) : 2-combo, split2 out
    tc_gemm<1,1,4><<<dim3((ROWS_E/128)*(HH/128), EE), 256, SMB1>>>(
        xs, (ll)BT*CC, ROWS_E, we1t, 0, be1, HH,
        ehs, (ll)EE*ROWS_E*HH, ROWS_E, stok, ROWS_E, HH, CC, ROWS_E/128, HH/128);

    // 6) ey[e] = eh[e] @ We2[e] + be2[e] : 2-combo, fp32 out
    tc_gemm<1,0,4><<<dim3((ROWS_E/128)*(CC/128), EE), 256, SMB1>>>(
        ehs, (ll)EE*ROWS_E*HH, ROWS_E, we2t, 0, be2, CC,
        ey, 0, ROWS_E, nullptr, 0, CC, HH, ROWS_E/128, CC/128);

    // 7) combine
    combine_kernel<<<BT, 256>>>(ey, tp, dest, out);
}

// round 16
// speedup vs baseline: 2.0982x; 1.0972x over previous
#include <cuda_runtime.h>
#include <cuda_fp16.h>
#include <stdint.h>

#define BB   8
#define TT   2048
#define CC   1024
#define EE   8
#define KTOP 2
#define CAPQ 320
#define HH   4096
#define BT   (BB*TT)
#define NSLOT (EE*BB*CAPQ)
#define ROWS_E (BB*CAPQ)
#define FIXCAP 1280
#define FIX_THRESH 4e-3f

typedef __half hf;
typedef long long ll;

// ---------------- scratch ----------------
__device__ hf    g_xs  [2ll*BT*CC];        // x split2
__device__ hf    g_wr1t[2ll*CC*HH];        // router weights split2 (fixup uses mid)
__device__ hf    g_wr2t[2ll*HH*HH];
__device__ hf    g_we1t[(ll)EE*CC*HH];     // expert weights: hi plane only
__device__ hf    g_we2t[(ll)EE*HH*CC];
__device__ hf    g_h1s [(ll)BT*HH];        // h1 hi plane only
__device__ hf    g_h2s [2ll*BT*HH];        // h2 split2 (router reads both)
__device__ hf    g_h1f [2ll*FIXCAP*HH];
__device__ hf    g_h2f [2ll*FIXCAP*HH];
__device__ hf    g_ehs [2ll*EE*ROWS_E*HH];
__device__ float g_ey  [(ll)EE*ROWS_E*CC];
__device__ float g_topk_p[BT*KTOP];
__device__ int   g_topk_e[BT*KTOP];
__device__ int   g_dest[BT*KTOP];
__device__ int   g_slot_tok[NSLOT];
__device__ int   g_fix_tok[FIXCAP];
__device__ int   g_fix_cnt;

// ---------------- PTX helpers ----------------
__device__ __forceinline__ uint32_t smem_u32(const void* p) {
    uint32_t a;
    asm("{ .reg .u64 t; cvta.to.shared.u64 t, %1; cvt.u32.u64 %0, t; }" : "=r"(a) : "l"(p));
    return a;
}
__device__ __forceinline__ void cp16(uint32_t dst, const void* src, int ssz) {
    asm volatile("cp.async.cg.shared.global [%0], [%1], 16, %2;" :: "r"(dst), "l"(src), "r"(ssz));
}
__device__ __forceinline__ void cp_commit() { asm volatile("cp.async.commit_group;" ::: "memory"); }
template<int N> __device__ __forceinline__ void cp_wait() {
    asm volatile("cp.async.wait_group %0;" :: "n"(N) : "memory");
}
__device__ __forceinline__ void ldsm4(uint32_t* r, uint32_t addr) {
    asm volatile("ldmatrix.sync.aligned.m8n8.x4.shared.b16 {%0,%1,%2,%3}, [%4];"
        : "=r"(r[0]), "=r"(r[1]), "=r"(r[2]), "=r"(r[3]) : "r"(addr));
}
__device__ __forceinline__ void ldsm4t(uint32_t* r, uint32_t addr) {
    asm volatile("ldmatrix.sync.aligned.m8n8.x4.trans.shared.b16 {%0,%1,%2,%3}, [%4];"
        : "=r"(r[0]), "=r"(r[1]), "=r"(r[2]), "=r"(r[3]) : "r"(addr));
}
__device__ __forceinline__ void mma_f16(float* c, const uint32_t* a, const uint32_t* b) {
    asm volatile("mma.sync.aligned.m16n8k16.row.col.f32.f16.f16.f32 "
        "{%0,%1,%2,%3}, {%4,%5,%6,%7}, {%8,%9}, {%0,%1,%2,%3};"
        : "+f"(c[0]), "+f"(c[1]), "+f"(c[2]), "+f"(c[3])
        : "r"(a[0]), "r"(a[1]), "r"(a[2]), "r"(a[3]), "r"(b[0]), "r"(b[1]));
}

// ---------------- fp16 split helpers ----------------
__device__ __forceinline__ void split2v(float v, uint16_t* h, uint16_t* m) {
    __half hb = __float2half_rn(v);
    __half mb = __float2half_rn(v - __half2float(hb));
    *h = *(uint16_t*)&hb; *m = *(uint16_t*)&mb;
}

__global__ __launch_bounds__(256)
void split2_kernel(const float* __restrict__ in, hf* __restrict__ out, ll ps) {
    ll i = ((ll)blockIdx.x * 256 + threadIdx.x) * 4;
    float4 v = *(const float4*)(in + i);
    uint16_t h[4], m[4];
    split2v(v.x, h+0, m+0); split2v(v.y, h+1, m+1);
    split2v(v.z, h+2, m+2); split2v(v.w, h+3, m+3);
    *(uint2*)(out + i)      = *(uint2*)h;
    *(uint2*)(out + ps + i) = *(uint2*)m;
}

__global__ __launch_bounds__(256)
void cvt_kernel(const float* __restrict__ in, hf* __restrict__ out) {
    ll i = ((ll)blockIdx.x * 256 + threadIdx.x) * 4;
    float4 v = *(const float4*)(in + i);
    __half2 lo = __floats2half2_rn(v.x, v.y);
    __half2 hi = __floats2half2_rn(v.z, v.w);
    uint2 pk = { *(uint32_t*)&lo, *(uint32_t*)&hi };
    *(uint2*)(out + i) = pk;
}

// ---------------- split-fp16 GEMM via mma.sync ----------------
// C = act( sum_{ia<NPA, ib<NPB, ia+ib<max(NPA,NPB)} A_plane[ia] @ B_plane[ib] + bias )
// Tile 128x128x32, 8 warps (4m x 2n), NSTG-stage cp.async ring, 1 barrier/chunk.
// OUTMODE: 0 = fp32; 1 = relu + split2 fp16 planes; 2 = relu + single fp16 plane.
#define PT_A 10240   // 128 rows x 80B
#define PT_B 8704    // 32 rows x 272B
template<int NPA, int NPB, int OUTMODE, int NSTG>
__global__ __launch_bounds__(256, 1)
void tc_gemm(const hf* __restrict__ A, ll ApS, int ArowsPerZ,
             const hf* __restrict__ B, ll BpS,
             const float* __restrict__ bias, int biasPerZ,
             void* __restrict__ outp, ll OpS, int MrowsPerZ,
             const int* __restrict__ gidx, int gstride,
             int N, int K, int gm, int gn)
{
    constexpr int stageB = NPA * PT_A + NPB * PT_B;
    constexpr int NA = 2 * NPA;
    constexpr int NB = 2 * NPB;
    constexpr int CMAX = (NPA > NPB) ? NPA : NPB;

    extern __shared__ char sm[];
    __shared__ int rowtok[128];
    const uint32_t smb = smem_u32(sm);
    const int tid = threadIdx.x;
    const int wid = tid >> 5, lane = tid & 31;
    const int z = blockIdx.y;

    int bid = blockIdx.x;
    int grp = bid / (gn * 8);
    int rem = bid - grp * gn * 8;
    int gsz = gm - grp * 8; if (gsz > 8) gsz = 8;
    int mtile = grp * 8 + rem % gsz;
    int ntile = rem / gsz;
    const int m0 = mtile << 7, n0 = ntile << 7;

    if (tid < 128)
        rowtok[tid] = gidx ? gidx[(ll)z * gstride + m0 + tid] : (z * ArowsPerZ + m0 + tid);
    __syncthreads();

    const int nch = K >> 5;
    const ll KN = (ll)K * N;
    const ll bstep = (ll)N * 64;

    const char* srcA[NA]; uint32_t dstA[NA]; uint32_t amask = 0;
    const char* srcB[NB]; uint32_t dstB[NB];
#pragma unroll
    for (int j = 0; j < NA; j++) {
        int u = tid + j * 256;
        int p = u >> 9, t = u & 511, r = t >> 2, c = t & 3;
        dstA[j] = (uint32_t)(p * PT_A + r * 80 + c * 16);
        int ra = rowtok[r];
        if (ra < 0) srcA[j] = (const char*)A;
        else { srcA[j] = (const char*)(A + (ll)p * ApS + (ll)ra * K + c * 8); amask |= 1u << j; }
    }
#pragma unroll
    for (int j = 0; j < NB; j++) {
        int u = tid + j * 256;
        int p = u >> 9, t = u & 511, r = t >> 4, c = t & 15;
        dstB[j] = (uint32_t)(NPA * PT_A + p * PT_B + r * 272 + c * 16);
        srcB[j] = (const char*)(B + (ll)p * BpS + (ll)z * KN + (ll)r * N + n0 + c * 8);
    }

    auto load_stage = [&](int s) {
        uint32_t sb = smb + s * stageB;
#pragma unroll
        for (int j = 0; j < NA; j++) {
            cp16(sb + dstA[j], srcA[j], (amask >> j & 1) ? 16 : 0);
            srcA[j] += 64;
        }
#pragma unroll
        for (int j = 0; j < NB; j++) {
            cp16(sb + dstB[j], srcB[j], 16);
            srcB[j] += bstep;
        }
        cp_commit();
    };

    const int wm = wid & 3, wn = wid >> 2;
    const uint32_t a_off = (uint32_t)((wm * 32 + (lane & 15)) * 80 + (lane >> 4) * 16);
    const uint32_t b_off = (uint32_t)((lane & 15) * 272 + (lane >> 4) * 16);

    float acc[2][8][4];
#pragma unroll
    for (int mt = 0; mt < 2; mt++)
#pragma unroll
        for (int nt = 0; nt < 8; nt++)
#pragma unroll
            for (int j = 0; j < 4; j++) acc[mt][nt][j] = 0.f;

#pragma unroll
    for (int s = 0; s < NSTG - 1; s++)
        if (s < nch) load_stage(s);

    int cur = 0;
    for (int i = 0; i < nch; i++) {
        int rem_groups = nch - 1 - i;
        if (i + NSTG - 1 < nch) cp_wait<NSTG - 2>();
        else if (rem_groups >= NSTG - 2) cp_wait<NSTG - 2>();
        else if (NSTG >= 4 && rem_groups == 2) cp_wait<2>();
        else if (rem_groups == 1) cp_wait<1>();
        else cp_wait<0>();
        __syncthreads();
        if (i + NSTG - 1 < nch) {
            int ns = cur + NSTG - 1;
            if (ns >= NSTG) ns -= NSTG;
            load_stage(ns);
        }

        uint32_t sbase = smb + cur * stageB;
#pragma unroll
        for (int ks = 0; ks < 2; ks++) {
            uint32_t aF[NPA][2][4];
#pragma unroll
            for (int p = 0; p < NPA; p++)
#pragma unroll
                for (int mt = 0; mt < 2; mt++)
                    ldsm4(aF[p][mt], sbase + p * PT_A + mt * 16 * 80 + ks * 32 + a_off);
#pragma unroll
            for (int ib = 0; ib < NPB; ib++) {
                uint32_t bF[8][2];
#pragma unroll
                for (int q = 0; q < 4; q++) {
                    uint32_t r4[4];
                    ldsm4t(r4, sbase + NPA * PT_A + ib * PT_B + ks * 4352
                               + (uint32_t)((wn * 64 + q * 16) * 2) + b_off);
                    bF[q*2][0] = r4[0]; bF[q*2][1] = r4[1];
                    bF[q*2+1][0] = r4[2]; bF[q*2+1][1] = r4[3];
                }
#pragma unroll
                for (int ia = 0; ia < NPA; ia++) {
                    if (ia + ib >= CMAX) continue;
#pragma unroll
                    for (int mt = 0; mt < 2; mt++)
#pragma unroll
                        for (int nt = 0; nt < 8; nt++)
                            mma_f16(acc[mt][nt], aF[ia][mt], bF[nt]);
                }
            }
        }
        cur++; if (cur == NSTG) cur = 0;
    }

    // ---- epilogue ----
    __syncthreads();
    float* ep = (float*)sm;
#pragma unroll
    for (int mt = 0; mt < 2; mt++) {
        int r0 = wm * 32 + mt * 16 + (lane >> 2);
#pragma unroll
        for (int nt = 0; nt < 8; nt++) {
            int col = wn * 64 + nt * 8 + (lane & 3) * 2;
            ep[r0 * 132 + col]       = acc[mt][nt][0];
            ep[r0 * 132 + col + 1]   = acc[mt][nt][1];
            ep[(r0+8) * 132 + col]   = acc[mt][nt][2];
            ep[(r0+8) * 132 + col+1] = acc[mt][nt][3];
        }
    }
    __syncthreads();

    {
        int r = tid >> 1, half = tid & 1;
        ll row = (ll)z * MrowsPerZ + m0 + r;
        int cbase = half * 64;
        const float* bb = bias + (ll)z * biasPerZ + n0 + cbase;
#pragma unroll
        for (int q = 0; q < 8; q++) {
            float v[8];
#pragma unroll
            for (int j = 0; j < 8; j++)
                v[j] = ep[r * 132 + cbase + q * 8 + j] + bb[q * 8 + j];
            if (OUTMODE == 0) {
                float* o = (float*)outp + row * (ll)N + n0 + cbase + q * 8;
                float4 o0 = {v[0], v[1], v[2], v[3]};
                float4 o1 = {v[4], v[5], v[6], v[7]};
                ((float4*)o)[0] = o0; ((float4*)o)[1] = o1;
            } else if (OUTMODE == 1) {
                __align__(16) uint16_t hs[8], ms[8];
#pragma unroll
                for (int j = 0; j < 8; j++) {
                    float vv = fmaxf(v[j], 0.f);
                    split2v(vv, hs + j, ms + j);
                }
                hf* o0 = (hf*)outp + row * (ll)N + n0 + cbase + q * 8;
                *(uint4*)o0 = *(uint4*)hs;
                *(uint4*)(o0 + OpS) = *(uint4*)ms;
            } else {
                __align__(16) uint16_t hs[8];
#pragma unroll
                for (int j = 0; j < 8; j++) {
                    __half hb = __float2half_rn(fmaxf(v[j], 0.f));
                    hs[j] = *(uint16_t*)&hb;
                }
                hf* o0 = (hf*)outp + row * (ll)N + n0 + cbase + q * 8;
                *(uint4*)o0 = *(uint4*)hs;
            }
        }
    }
}

// ---------------- router: logits from 2 fp16 planes, softmax, top-2 ----------------
__device__ __forceinline__ void router_logits_warp(const hf* r0, ll ps, const float* Wr3,
                                                   int lane, float* acc)
{
#pragma unroll
    for (int e = 0; e < EE; e++) acc[e] = 0.f;
    for (int k = lane * 4; k < HH; k += 128) {
        float vv[4];
#pragma unroll
        for (int h = 0; h < 2; h++) {
            __half2 a = *(const __half2*)(r0 + k + 2 * h);
            __half2 b = *(const __half2*)(r0 + ps + k + 2 * h);
            float2 fa = __half22float2(a), fb = __half22float2(b);
            vv[2*h+0] = fa.x + fb.x;
            vv[2*h+1] = fa.y + fb.y;
        }
#pragma unroll
        for (int j = 0; j < 4; j++) {
            const float* w = Wr3 + (ll)(k + j) * EE;
            float xv = vv[j];
#pragma unroll
            for (int e = 0; e < EE; e++) acc[e] += xv * w[e];
        }
    }
#pragma unroll
    for (int e = 0; e < EE; e++)
#pragma unroll
        for (int off = 16; off > 0; off >>= 1)
            acc[e] += __shfl_xor_sync(0xFFFFFFFFu, acc[e], off);
}

__device__ __forceinline__ void topk_write(const float* accv, const float* br3,
                                           float* tp, int* te, int tok,
                                           int* fix_tok, int* fix_cnt)
{
    float lg[EE], mx = -1e30f;
#pragma unroll
    for (int e = 0; e < EE; e++) { lg[e] = accv[e] + br3[e]; mx = fmaxf(mx, lg[e]); }
    float p[EE], s = 0.f;
#pragma unroll
    for (int e = 0; e < EE; e++) { p[e] = __expf(lg[e] - mx); s += p[e]; }
    float inv = 1.f / s;
    int i0 = 0;
#pragma unroll
    for (int e = 1; e < EE; e++) if (lg[e] > lg[i0]) i0 = e;
    int i1 = (i0 == 0) ? 1 : 0;
#pragma unroll
    for (int e = 0; e < EE; e++) if (e != i0 && lg[e] > lg[i1]) i1 = e;
    if (fix_tok) {
        float l3 = -1e30f;
#pragma unroll
        for (int e = 0; e < EE; e++) if (e != i0 && e != i1) l3 = fmaxf(l3, lg[e]);
        if (lg[i1] - l3 < FIX_THRESH) {
            int ix = atomicAdd(fix_cnt, 1);
            if (ix < FIXCAP) fix_tok[ix] = tok;
        }
    }
    tp[tok * 2 + 0] = p[i0] * inv;
    tp[tok * 2 + 1] = p[i1] * inv;
    te[tok * 2 + 0] = i0;
    te[tok * 2 + 1] = i1;
}

__global__ __launch_bounds__(128)
void router_topk2_kernel(const hf* __restrict__ h2s, ll ps,
                         const float* __restrict__ Wr3, const float* __restrict__ br3,
                         float* __restrict__ tp, int* __restrict__ te,
                         int* __restrict__ fix_tok, int* __restrict__ fix_cnt)
{
    int tok = (blockIdx.x * blockDim.x + threadIdx.x) >> 5;
    int lane = threadIdx.x & 31;
    if (tok >= BT) return;
    float acc[EE];
    router_logits_warp(h2s + (ll)tok * HH, ps, Wr3, lane, acc);
    if (lane == 0) topk_write(acc, br3, tp, te, tok, fix_tok, fix_cnt);
}

__global__ __launch_bounds__(128)
void router_fix_kernel(const hf* __restrict__ h2f, ll ps,
                       const float* __restrict__ Wr3, const float* __restrict__ br3,
                       const int* __restrict__ fix_tok,
                       float* __restrict__ tp, int* __restrict__ te)
{
    int r = (blockIdx.x * blockDim.x + threadIdx.x) >> 5;
    int lane = threadIdx.x & 31;
    if (r >= FIXCAP) return;
    int tok = fix_tok[r];
    if (tok < 0) return;
    float acc[EE];
    router_logits_warp(h2f + (ll)r * HH, ps, Wr3, lane, acc);
    if (lane == 0) topk_write(acc, br3, tp, te, tok, nullptr, nullptr);
}

__global__ void init_fix_kernel(int* fix_tok, int* fix_cnt, int* slot_tok) {
    int i = blockIdx.x * 256 + threadIdx.x;
    if (i < FIXCAP) fix_tok[i] = -1;
    if (i == 0) *fix_cnt = 0;
    if (i < NSLOT) slot_tok[i] = -1;
}

__global__ __launch_bounds__(256)
void route_scan_kernel(const int* __restrict__ te, int* __restrict__ dest, int* __restrict__ slot_tok)
{
    __shared__ int se[TT * KTOP];
    int b = blockIdx.x;
    for (int i = threadIdx.x; i < TT * KTOP; i += 256) se[i] = te[b * TT * KTOP + i];
    __syncthreads();
    if (threadIdx.x < EE) {
        int e = threadIdx.x, cnt = 0;
        for (int i = 0; i < TT * KTOP; i++) {
            if (se[i] == e) {
                int gi = b * TT * KTOP + i;
                if (cnt < CAPQ) {
                    int s = e * (BB * CAPQ) + b * CAPQ + cnt;
                    dest[gi] = s;
                    slot_tok[s] = b * TT + (i >> 1);
                } else dest[gi] = -1;
                cnt++;
            }
        }
    }
}

__global__ __launch_bounds__(256)
void combine_kernel(const float* __restrict__ ey, const float* __restrict__ topk_p,
                    const int* __restrict__ dest, float* __restrict__ out)
{
    int tok = blockIdx.x;
    int c = threadIdx.x * 4;
    float4 r = make_float4(0.f, 0.f, 0.f, 0.f);
#pragma unroll
    for (int k = 0; k < KTOP; k++) {
        int s = dest[tok * 2 + k];
        if (s >= 0) {
            float p = topk_p[tok * 2 + k];
            float4 v = *(const float4*)(ey + (ll)s * CC + c);
            r.x += p * v.x; r.y += p * v.y; r.z += p * v.z; r.w += p * v.w;
        }
    }
    *(float4*)(out + (ll)tok * CC + c) = r;
}

// ---------------- launch ----------------
extern "C" void kernel_launch(void* const* d_in, const int* in_sizes, int n_in,
                              void* d_out, int out_size)
{
    (void)in_sizes; (void)n_in; (void)out_size;
    const float* x   = (const float*)d_in[0];
    const float* Wr1 = (const float*)d_in[1];
    const float* br1 = (const float*)d_in[2];
    const float* Wr2 = (const float*)d_in[3];
    const float* br2 = (const float*)d_in[4];
    const float* Wr3 = (const float*)d_in[5];
    const float* br3 = (const float*)d_in[6];
    const float* We1 = (const float*)d_in[7];
    const float* be1 = (const float*)d_in[8];
    const float* We2 = (const float*)d_in[9];
    const float* be2 = (const float*)d_in[10];
    float* out = (float*)d_out;

    hf *xs, *wr1t, *wr2t, *we1t, *we2t, *h1s, *h2s, *h1f, *h2f, *ehs;
    float *ey, *tp; int *te, *dest, *stok, *ftok, *fcnt;
    cudaGetSymbolAddress((void**)&xs,   g_xs);
    cudaGetSymbolAddress((void**)&wr1t, g_wr1t);
    cudaGetSymbolAddress((void**)&wr2t, g_wr2t);
    cudaGetSymbolAddress((void**)&we1t, g_we1t);
    cudaGetSymbolAddress((void**)&we2t, g_we2t);
    cudaGetSymbolAddress((void**)&h1s,  g_h1s);
    cudaGetSymbolAddress((void**)&h2s,  g_h2s);
    cudaGetSymbolAddress((void**)&h1f,  g_h1f);
    cudaGetSymbolAddress((void**)&h2f,  g_h2f);
    cudaGetSymbolAddress((void**)&ehs,  g_ehs);
    cudaGetSymbolAddress((void**)&ey,   g_ey);
    cudaGetSymbolAddress((void**)&tp,   g_topk_p);
    cudaGetSymbolAddress((void**)&te,   g_topk_e);
    cudaGetSymbolAddress((void**)&dest, g_dest);
    cudaGetSymbolAddress((void**)&stok, g_slot_tok);
    cudaGetSymbolAddress((void**)&ftok, g_fix_tok);
    cudaGetSymbolAddress((void**)&fcnt, g_fix_cnt);

    const int SM21 = 4 * (2 * PT_A + 1 * PT_B);   // 116736 (NPA=2,NPB=1)
    const int SM11 = 4 * (1 * PT_A + 1 * PT_B);   //  75776 (NPA=1,NPB=1)
    const int SM22 = 4 * (2 * PT_A + 2 * PT_B);   // 151552 (NPA=2,NPB=2)
    static int smem_set = 0;
    if (!smem_set) {
        cudaFuncSetAttribute(tc_gemm<2,1,2,4>, cudaFuncAttributeMaxDynamicSharedMemorySize, SM21);
        cudaFuncSetAttribute(tc_gemm<1,1,1,4>, cudaFuncAttributeMaxDynamicSharedMemorySize, SM11);
        cudaFuncSetAttribute(tc_gemm<2,2,1,4>, cudaFuncAttributeMaxDynamicSharedMemorySize, SM22);
        cudaFuncSetAttribute(tc_gemm<2,1,1,4>, cudaFuncAttributeMaxDynamicSharedMemorySize, SM21);
        cudaFuncSetAttribute(tc_gemm<2,1,0,4>, cudaFuncAttributeMaxDynamicSharedMemorySize, SM21);
        smem_set = 1;
    }

    // 0) prep: x + router weights split2; expert weights hi-plane convert; table init
    split2_kernel<<<(ll)BT * CC / 1024, 256>>>(x,   xs,   (ll)BT * CC);
    split2_kernel<<<(ll)CC * HH / 1024, 256>>>(Wr1, wr1t, (ll)CC * HH);
    split2_kernel<<<(ll)HH * HH / 1024, 256>>>(Wr2, wr2t, (ll)HH * HH);
    cvt_kernel<<<(ll)EE * CC * HH / 1024, 256>>>(We1, we1t);
    cvt_kernel<<<(ll)EE * HH * CC / 1024, 256>>>(We2, we2t);
    init_fix_kernel<<<(NSLOT + 255) / 256, 256>>>(ftok, fcnt, stok);

    // 1) h1 = relu(x @ Wr1 + br1) : 2-combo (fullA x hiB), single-plane fp16 out
    tc_gemm<2,1,2,4><<<dim3((BT/128)*(HH/128), 1), 256, SM21>>>(
        xs, (ll)BT*CC, BT, wr1t, 0, br1, 0,
        h1s, 0, BT, nullptr, 0, HH, CC, BT/128, HH/128);

    // 2) h2 = relu(h1 @ Wr2 + br2) : 1-combo (hiA x hiB), split2 out
    tc_gemm<1,1,1,4><<<dim3((BT/128)*(HH/128), 1), 256, SM11>>>(
        h1s, 0, BT, wr2t, 0, br2, 0,
        h2s, (ll)BT*HH, BT, nullptr, 0, HH, HH, BT/128, HH/128);

    // 3) logits -> softmax -> top-2, flag marginal tokens (gap23 < 4e-3)
    router_topk2_kernel<<<(BT * 32) / 128, 128>>>(h2s, (ll)BT*HH, Wr3, br3, tp, te, ftok, fcnt);

    // 3b) near-exact (3-combo, err ~2^-22) fixup chain for flagged tokens
    tc_gemm<2,2,1,4><<<dim3((FIXCAP/128)*(HH/128), 1), 256, SM22>>>(
        xs, (ll)BT*CC, FIXCAP, wr1t, (ll)CC*HH, br1, 0,
        h1f, (ll)FIXCAP*HH, FIXCAP, ftok, FIXCAP, HH, CC, FIXCAP/128, HH/128);
    tc_gemm<2,2,1,4><<<dim3((FIXCAP/128)*(HH/128), 1), 256, SM22>>>(
        h1f, (ll)FIXCAP*HH, FIXCAP, wr2t, (ll)HH*HH, br2, 0,
        h2f, (ll)FIXCAP*HH, FIXCAP, nullptr, 0, HH, HH, FIXCAP/128, HH/128);
    router_fix_kernel<<<(FIXCAP * 32) / 128, 128>>>(h2f, (ll)FIXCAP*HH, Wr3, br3, ftok, tp, te);

    // 4) routing tables
    route_scan_kernel<<<BB, 256>>>(te, dest, stok);

    // 5) eh[e] = relu(gather(x) @ We1[e] + be1[e]) : 2-combo, split2 out
    tc_gemm<2,1,1,4><<<dim3((ROWS_E/128)*(HH/128), EE), 256, SM21>>>(
        xs, (ll)BT*CC, ROWS_E, we1t, 0, be1, HH,
        ehs, (ll)EE*ROWS_E*HH, ROWS_E, stok, ROWS_E, HH, CC, ROWS_E/128, HH/128);

    // 6) ey[e] = eh[e] @ We2[e] + be2[e] : 2-combo, fp32 out
    tc_gemm<2,1,0,4><<<dim3((ROWS_E/128)*(CC/128), EE), 256, SM21>>>(
        ehs, (ll)EE*ROWS_E*HH, ROWS_E, we2t, 0, be2, CC,
        ey, 0, ROWS_E, nullptr, 0, CC, HH, ROWS_E/128, CC/128);

    // 7) combine
    combine_kernel<<<BT, 256>>>(ey, tp, dest, out);
}

// round 17
// speedup vs baseline: 2.3172x; 1.1044x over previous
#include <cuda_runtime.h>
#include <cuda_fp16.h>
#include <stdint.h>

#define BB   8
#define TT   2048
#define CC   1024
#define EE   8
#define KTOP 2
#define CAPQ 320
#define HH   4096
#define BT   (BB*TT)
#define NSLOT (EE*BB*CAPQ)
#define ROWS_E (BB*CAPQ)
#define FIXCAP 1280
#define FIX_THRESH 4e-3f

typedef __half hf;
typedef long long ll;

// ---------------- scratch ----------------
__device__ hf    g_xs  [2ll*BT*CC];        // x split2 (fixup + h1 use both planes)
__device__ hf    g_wr1t[2ll*CC*HH];        // router weights split2 (fixup uses mid)
__device__ hf    g_wr2t[2ll*HH*HH];
__device__ hf    g_we1t[(ll)EE*CC*HH];     // expert weights: hi plane only
__device__ hf    g_we2t[(ll)EE*HH*CC];
__device__ hf    g_h1s [(ll)BT*HH];        // h1 hi plane only
__device__ hf    g_h2s [2ll*BT*HH];        // h2 split2 (router reads both)
__device__ hf    g_h1f [2ll*FIXCAP*HH];
__device__ hf    g_h2f [2ll*FIXCAP*HH];
__device__ hf    g_ehs [(ll)EE*ROWS_E*HH]; // eh hi plane only
__device__ float g_ey  [(ll)EE*ROWS_E*CC];
__device__ float g_topk_p[BT*KTOP];
__device__ int   g_topk_e[BT*KTOP];
__device__ int   g_dest[BT*KTOP];
__device__ int   g_slot_tok[NSLOT];
__device__ int   g_fix_tok[FIXCAP];
__device__ int   g_fix_cnt;

// ---------------- PTX helpers ----------------
__device__ __forceinline__ uint32_t smem_u32(const void* p) {
    uint32_t a;
    asm("{ .reg .u64 t; cvta.to.shared.u64 t, %1; cvt.u32.u64 %0, t; }" : "=r"(a) : "l"(p));
    return a;
}
__device__ __forceinline__ void cp16(uint32_t dst, const void* src, int ssz) {
    asm volatile("cp.async.cg.shared.global [%0], [%1], 16, %2;" :: "r"(dst), "l"(src), "r"(ssz));
}
__device__ __forceinline__ void cp_commit() { asm volatile("cp.async.commit_group;" ::: "memory"); }
template<int N> __device__ __forceinline__ void cp_wait() {
    asm volatile("cp.async.wait_group %0;" :: "n"(N) : "memory");
}
__device__ __forceinline__ void ldsm4(uint32_t* r, uint32_t addr) {
    asm volatile("ldmatrix.sync.aligned.m8n8.x4.shared.b16 {%0,%1,%2,%3}, [%4];"
        : "=r"(r[0]), "=r"(r[1]), "=r"(r[2]), "=r"(r[3]) : "r"(addr));
}
__device__ __forceinline__ void ldsm4t(uint32_t* r, uint32_t addr) {
    asm volatile("ldmatrix.sync.aligned.m8n8.x4.trans.shared.b16 {%0,%1,%2,%3}, [%4];"
        : "=r"(r[0]), "=r"(r[1]), "=r"(r[2]), "=r"(r[3]) : "r"(addr));
}
__device__ __forceinline__ void mma_f16(float* c, const uint32_t* a, const uint32_t* b) {
    asm volatile("mma.sync.aligned.m16n8k16.row.col.f32.f16.f16.f32 "
        "{%0,%1,%2,%3}, {%4,%5,%6,%7}, {%8,%9}, {%0,%1,%2,%3};"
        : "+f"(c[0]), "+f"(c[1]), "+f"(c[2]), "+f"(c[3])
        : "r"(a[0]), "r"(a[1]), "r"(a[2]), "r"(a[3]), "r"(b[0]), "r"(b[1]));
}

// ---------------- fp16 split helpers ----------------
__device__ __forceinline__ void split2v(float v, uint16_t* h, uint16_t* m) {
    __half hb = __float2half_rn(v);
    __half mb = __float2half_rn(v - __half2float(hb));
    *h = *(uint16_t*)&hb; *m = *(uint16_t*)&mb;
}

__global__ __launch_bounds__(256)
void split2_kernel(const float* __restrict__ in, hf* __restrict__ out, ll ps) {
    ll i = ((ll)blockIdx.x * 256 + threadIdx.x) * 4;
    float4 v = *(const float4*)(in + i);
    uint16_t h[4], m[4];
    split2v(v.x, h+0, m+0); split2v(v.y, h+1, m+1);
    split2v(v.z, h+2, m+2); split2v(v.w, h+3, m+3);
    *(uint2*)(out + i)      = *(uint2*)h;
    *(uint2*)(out + ps + i) = *(uint2*)m;
}

__global__ __launch_bounds__(256)
void cvt_kernel(const float* __restrict__ in, hf* __restrict__ out) {
    ll i = ((ll)blockIdx.x * 256 + threadIdx.x) * 4;
    float4 v = *(const float4*)(in + i);
    __half2 lo = __floats2half2_rn(v.x, v.y);
    __half2 hi = __floats2half2_rn(v.z, v.w);
    uint2 pk = { *(uint32_t*)&lo, *(uint32_t*)&hi };
    *(uint2*)(out + i) = pk;
}

// ---------------- split-fp16 GEMM via mma.sync ----------------
// C = act( sum_{ia<NPA, ib<NPB, ia+ib<max(NPA,NPB)} A_plane[ia] @ B_plane[ib] + bias )
// Tile 128x128x32, 8 warps (4m x 2n), NSTG-stage cp.async ring, 1 barrier/chunk.
// OUTMODE: 0 = fp32; 1 = relu + split2 fp16 planes; 2 = relu + single fp16 plane.
#define PT_A 10240   // 128 rows x 80B
#define PT_B 8704    // 32 rows x 272B
template<int NPA, int NPB, int OUTMODE, int NSTG>
__global__ __launch_bounds__(256, 1)
void tc_gemm(const hf* __restrict__ A, ll ApS, int ArowsPerZ,
             const hf* __restrict__ B, ll BpS,
             const float* __restrict__ bias, int biasPerZ,
             void* __restrict__ outp, ll OpS, int MrowsPerZ,
             const int* __restrict__ gidx, int gstride,
             int N, int K, int gm, int gn)
{
    constexpr int stageB = NPA * PT_A + NPB * PT_B;
    constexpr int NA = 2 * NPA;
    constexpr int NB = 2 * NPB;
    constexpr int CMAX = (NPA > NPB) ? NPA : NPB;

    extern __shared__ char sm[];
    __shared__ int rowtok[128];
    const uint32_t smb = smem_u32(sm);
    const int tid = threadIdx.x;
    const int wid = tid >> 5, lane = tid & 31;
    const int z = blockIdx.y;

    int bid = blockIdx.x;
    int grp = bid / (gn * 8);
    int rem = bid - grp * gn * 8;
    int gsz = gm - grp * 8; if (gsz > 8) gsz = 8;
    int mtile = grp * 8 + rem % gsz;
    int ntile = rem / gsz;
    const int m0 = mtile << 7, n0 = ntile << 7;

    if (tid < 128)
        rowtok[tid] = gidx ? gidx[(ll)z * gstride + m0 + tid] : (z * ArowsPerZ + m0 + tid);
    __syncthreads();

    const int nch = K >> 5;
    const ll KN = (ll)K * N;
    const ll bstep = (ll)N * 64;

    const char* srcA[NA]; uint32_t dstA[NA]; uint32_t amask = 0;
    const char* srcB[NB]; uint32_t dstB[NB];
#pragma unroll
    for (int j = 0; j < NA; j++) {
        int u = tid + j * 256;
        int p = u >> 9, t = u & 511, r = t >> 2, c = t & 3;
        dstA[j] = (uint32_t)(p * PT_A + r * 80 + c * 16);
        int ra = rowtok[r];
        if (ra < 0) srcA[j] = (const char*)A;
        else { srcA[j] = (const char*)(A + (ll)p * ApS + (ll)ra * K + c * 8); amask |= 1u << j; }
    }
#pragma unroll
    for (int j = 0; j < NB; j++) {
        int u = tid + j * 256;
        int p = u >> 9, t = u & 511, r = t >> 4, c = t & 15;
        dstB[j] = (uint32_t)(NPA * PT_A + p * PT_B + r * 272 + c * 16);
        srcB[j] = (const char*)(B + (ll)p * BpS + (ll)z * KN + (ll)r * N + n0 + c * 8);
    }

    auto load_stage = [&](int s) {
        uint32_t sb = smb + s * stageB;
#pragma unroll
        for (int j = 0; j < NA; j++) {
            cp16(sb + dstA[j], srcA[j], (amask >> j & 1) ? 16 : 0);
            srcA[j] += 64;
        }
#pragma unroll
        for (int j = 0; j < NB; j++) {
            cp16(sb + dstB[j], srcB[j], 16);
            srcB[j] += bstep;
        }
        cp_commit();
    };

    const int wm = wid & 3, wn = wid >> 2;
    const uint32_t a_off = (uint32_t)((wm * 32 + (lane & 15)) * 80 + (lane >> 4) * 16);
    const uint32_t b_off = (uint32_t)((lane & 15) * 272 + (lane >> 4) * 16);

    float acc[2][8][4];
#pragma unroll
    for (int mt = 0; mt < 2; mt++)
#pragma unroll
        for (int nt = 0; nt < 8; nt++)
#pragma unroll
            for (int j = 0; j < 4; j++) acc[mt][nt][j] = 0.f;

#pragma unroll
    for (int s = 0; s < NSTG - 1; s++)
        if (s < nch) load_stage(s);

    int cur = 0;
    for (int i = 0; i < nch; i++) {
        int rem_groups = nch - 1 - i;
        if (i + NSTG - 1 < nch) cp_wait<NSTG - 2>();
        else if (rem_groups >= NSTG - 2) cp_wait<NSTG - 2>();
        else if (NSTG >= 4 && rem_groups == 2) cp_wait<2>();
        else if (rem_groups == 1) cp_wait<1>();
        else cp_wait<0>();
        __syncthreads();
        if (i + NSTG - 1 < nch) {
            int ns = cur + NSTG - 1;
            if (ns >= NSTG) ns -= NSTG;
            load_stage(ns);
        }

        uint32_t sbase = smb + cur * stageB;
#pragma unroll
        for (int ks = 0; ks < 2; ks++) {
            uint32_t aF[NPA][2][4];
#pragma unroll
            for (int p = 0; p < NPA; p++)
#pragma unroll
                for (int mt = 0; mt < 2; mt++)
                    ldsm4(aF[p][mt], sbase + p * PT_A + mt * 16 * 80 + ks * 32 + a_off);
#pragma unroll
            for (int ib = 0; ib < NPB; ib++) {
                uint32_t bF[8][2];
#pragma unroll
                for (int q = 0; q < 4; q++) {
                    uint32_t r4[4];
                    ldsm4t(r4, sbase + NPA * PT_A + ib * PT_B + ks * 4352
                               + (uint32_t)((wn * 64 + q * 16) * 2) + b_off);
                    bF[q*2][0] = r4[0]; bF[q*2][1] = r4[1];
                    bF[q*2+1][0] = r4[2]; bF[q*2+1][1] = r4[3];
                }
#pragma unroll
                for (int ia = 0; ia < NPA; ia++) {
                    if (ia + ib >= CMAX) continue;
#pragma unroll
                    for (int mt = 0; mt < 2; mt++)
#pragma unroll
                        for (int nt = 0; nt < 8; nt++)
                            mma_f16(acc[mt][nt], aF[ia][mt], bF[nt]);
                }
            }
        }
        cur++; if (cur == NSTG) cur = 0;
    }

    // ---- epilogue ----
    __syncthreads();
    float* ep = (float*)sm;
#pragma unroll
    for (int mt = 0; mt < 2; mt++) {
        int r0 = wm * 32 + mt * 16 + (lane >> 2);
#pragma unroll
        for (int nt = 0; nt < 8; nt++) {
            int col = wn * 64 + nt * 8 + (lane & 3) * 2;
            ep[r0 * 132 + col]       = acc[mt][nt][0];
            ep[r0 * 132 + col + 1]   = acc[mt][nt][1];
            ep[(r0+8) * 132 + col]   = acc[mt][nt][2];
            ep[(r0+8) * 132 + col+1] = acc[mt][nt][3];
        }
    }
    __syncthreads();

    {
        int r = tid >> 1, half = tid & 1;
        ll row = (ll)z * MrowsPerZ + m0 + r;
        int cbase = half * 64;
        const float* bb = bias + (ll)z * biasPerZ + n0 + cbase;
#pragma unroll
        for (int q = 0; q < 8; q++) {
            float v[8];
#pragma unroll
            for (int j = 0; j < 8; j++)
                v[j] = ep[r * 132 + cbase + q * 8 + j] + bb[q * 8 + j];
            if (OUTMODE == 0) {
                float* o = (float*)outp + row * (ll)N + n0 + cbase + q * 8;
                float4 o0 = {v[0], v[1], v[2], v[3]};
                float4 o1 = {v[4], v[5], v[6], v[7]};
                ((float4*)o)[0] = o0; ((float4*)o)[1] = o1;
            } else if (OUTMODE == 1) {
                __align__(16) uint16_t hs[8], ms[8];
#pragma unroll
                for (int j = 0; j < 8; j++) {
                    float vv = fmaxf(v[j], 0.f);
                    split2v(vv, hs + j, ms + j);
                }
                hf* o0 = (hf*)outp + row * (ll)N + n0 + cbase + q * 8;
                *(uint4*)o0 = *(uint4*)hs;
                *(uint4*)(o0 + OpS) = *(uint4*)ms;
            } else {
                __align__(16) uint16_t hs[8];
#pragma unroll
                for (int j = 0; j < 8; j++) {
                    __half hb = __float2half_rn(fmaxf(v[j], 0.f));
                    hs[j] = *(uint16_t*)&hb;
                }
                hf* o0 = (hf*)outp + row * (ll)N + n0 + cbase + q * 8;
                *(uint4*)o0 = *(uint4*)hs;
            }
        }
    }
}

// ---------------- router: logits from 2 fp16 planes, softmax, top-2 ----------------
__device__ __forceinline__ void router_logits_warp(const hf* r0, ll ps, const float* Wr3,
                                                   int lane, float* acc)
{
#pragma unroll
    for (int e = 0; e < EE; e++) acc[e] = 0.f;
    for (int k = lane * 4; k < HH; k += 128) {
        float vv[4];
#pragma unroll
        for (int h = 0; h < 2; h++) {
            __half2 a = *(const __half2*)(r0 + k + 2 * h);
            __half2 b = *(const __half2*)(r0 + ps + k + 2 * h);
            float2 fa = __half22float2(a), fb = __half22float2(b);
            vv[2*h+0] = fa.x + fb.x;
            vv[2*h+1] = fa.y + fb.y;
        }
#pragma unroll
        for (int j = 0; j < 4; j++) {
            const float* w = Wr3 + (ll)(k + j) * EE;
            float xv = vv[j];
#pragma unroll
            for (int e = 0; e < EE; e++) acc[e] += xv * w[e];
        }
    }
#pragma unroll
    for (int e = 0; e < EE; e++)
#pragma unroll
        for (int off = 16; off > 0; off >>= 1)
            acc[e] += __shfl_xor_sync(0xFFFFFFFFu, acc[e], off);
}

__device__ __forceinline__ void topk_write(const float* accv, const float* br3,
                                           float* tp, int* te, int tok,
                                           int* fix_tok, int* fix_cnt)
{
    float lg[EE], mx = -1e30f;
#pragma unroll
    for (int e = 0; e < EE; e++) { lg[e] = accv[e] + br3[e]; mx = fmaxf(mx, lg[e]); }
    float p[EE], s = 0.f;
#pragma unroll
    for (int e = 0; e < EE; e++) { p[e] = __expf(lg[e] - mx); s += p[e]; }
    float inv = 1.f / s;
    int i0 = 0;
#pragma unroll
    for (int e = 1; e < EE; e++) if (lg[e] > lg[i0]) i0 = e;
    int i1 = (i0 == 0) ? 1 : 0;
#pragma unroll
    for (int e = 0; e < EE; e++) if (e != i0 && lg[e] > lg[i1]) i1 = e;
    if (fix_tok) {
        float l3 = -1e30f;
#pragma unroll
        for (int e = 0; e < EE; e++) if (e != i0 && e != i1) l3 = fmaxf(l3, lg[e]);
        if (lg[i1] - l3 < FIX_THRESH) {
            int ix = atomicAdd(fix_cnt, 1);
            if (ix < FIXCAP) fix_tok[ix] = tok;
        }
    }
    tp[tok * 2 + 0] = p[i0] * inv;
    tp[tok * 2 + 1] = p[i1] * inv;
    te[tok * 2 + 0] = i0;
    te[tok * 2 + 1] = i1;
}

__global__ __launch_bounds__(128)
void router_topk2_kernel(const hf* __restrict__ h2s, ll ps,
                         const float* __restrict__ Wr3, const float* __restrict__ br3,
                         float* __restrict__ tp, int* __restrict__ te,
                         int* __restrict__ fix_tok, int* __restrict__ fix_cnt)
{
    int tok = (blockIdx.x * blockDim.x + threadIdx.x) >> 5;
    int lane = threadIdx.x & 31;
    if (tok >= BT) return;
    float acc[EE];
    router_logits_warp(h2s + (ll)tok * HH, ps, Wr3, lane, acc);
    if (lane == 0) topk_write(acc, br3, tp, te, tok, fix_tok, fix_cnt);
}

__global__ __launch_bounds__(128)
void router_fix_kernel(const hf* __restrict__ h2f, ll ps,
                       const float* __restrict__ Wr3, const float* __restrict__ br3,
                       const int* __restrict__ fix_tok,
                       float* __restrict__ tp, int* __restrict__ te)
{
    int r = (blockIdx.x * blockDim.x + threadIdx.x) >> 5;
    int lane = threadIdx.x & 31;
    if (r >= FIXCAP) return;
    int tok = fix_tok[r];
    if (tok < 0) return;
    float acc[EE];
    router_logits_warp(h2f + (ll)r * HH, ps, Wr3, lane, acc);
    if (lane == 0) topk_write(acc, br3, tp, te, tok, nullptr, nullptr);
}

__global__ void init_fix_kernel(int* fix_tok, int* fix_cnt, int* slot_tok) {
    int i = blockIdx.x * 256 + threadIdx.x;
    if (i < FIXCAP) fix_tok[i] = -1;
    if (i == 0) *fix_cnt = 0;
    if (i < NSLOT) slot_tok[i] = -1;
}

__global__ __launch_bounds__(256)
void route_scan_kernel(const int* __restrict__ te, int* __restrict__ dest, int* __restrict__ slot_tok)
{
    __shared__ int se[TT * KTOP];
    int b = blockIdx.x;
    for (int i = threadIdx.x; i < TT * KTOP; i += 256) se[i] = te[b * TT * KTOP + i];
    __syncthreads();
    if (threadIdx.x < EE) {
        int e = threadIdx.x, cnt = 0;
        for (int i = 0; i < TT * KTOP; i++) {
            if (se[i] == e) {
                int gi = b * TT * KTOP + i;
                if (cnt < CAPQ) {
                    int s = e * (BB * CAPQ) + b * CAPQ + cnt;
                    dest[gi] = s;
                    slot_tok[s] = b * TT + (i >> 1);
                } else dest[gi] = -1;
                cnt++;
            }
        }
    }
}

__global__ __launch_bounds__(256)
void combine_kernel(const float* __restrict__ ey, const float* __restrict__ topk_p,
                    const int* __restrict__ dest, float* __restrict__ out)
{
    int tok = blockIdx.x;
    int c = threadIdx.x * 4;
    float4 r = make_float4(0.f, 0.f, 0.f, 0.f);
#pragma unroll
    for (int k = 0; k < KTOP; k++) {
        int s = dest[tok * 2 + k];
        if (s >= 0) {
            float p = topk_p[tok * 2 + k];
            float4 v = *(const float4*)(ey + (ll)s * CC + c);
            r.x += p * v.x; r.y += p * v.y; r.z += p * v.z; r.w += p * v.w;
        }
    }
    *(float4*)(out + (ll)tok * CC + c) = r;
}

// ---------------- launch ----------------
extern "C" void kernel_launch(void* const* d_in, const int* in_sizes, int n_in,
                              void* d_out, int out_size)
{
    (void)in_sizes; (void)n_in; (void)out_size;
    const float* x   = (const float*)d_in[0];
    const float* Wr1 = (const float*)d_in[1];
    const float* br1 = (const float*)d_in[2];
    const float* Wr2 = (const float*)d_in[3];
    const float* br2 = (const float*)d_in[4];
    const float* Wr3 = (const float*)d_in[5];
    const float* br3 = (const float*)d_in[6];
    const float* We1 = (const float*)d_in[7];
    const float* be1 = (const float*)d_in[8];
    const float* We2 = (const float*)d_in[9];
    const float* be2 = (const float*)d_in[10];
    float* out = (float*)d_out;

    hf *xs, *wr1t, *wr2t, *we1t, *we2t, *h1s, *h2s, *h1f, *h2f, *ehs;
    float *ey, *tp; int *te, *dest, *stok, *ftok, *fcnt;
    cudaGetSymbolAddress((void**)&xs,   g_xs);
    cudaGetSymbolAddress((void**)&wr1t, g_wr1t);
    cudaGetSymbolAddress((void**)&wr2t, g_wr2t);
    cudaGetSymbolAddress((void**)&we1t, g_we1t);
    cudaGetSymbolAddress((void**)&we2t, g_we2t);
    cudaGetSymbolAddress((void**)&h1s,  g_h1s);
    cudaGetSymbolAddress((void**)&h2s,  g_h2s);
    cudaGetSymbolAddress((void**)&h1f,  g_h1f);
    cudaGetSymbolAddress((void**)&h2f,  g_h2f);
    cudaGetSymbolAddress((void**)&ehs,  g_ehs);
    cudaGetSymbolAddress((void**)&ey,   g_ey);
    cudaGetSymbolAddress((void**)&tp,   g_topk_p);
    cudaGetSymbolAddress((void**)&te,   g_topk_e);
    cudaGetSymbolAddress((void**)&dest, g_dest);
    cudaGetSymbolAddress((void**)&stok, g_slot_tok);
    cudaGetSymbolAddress((void**)&ftok, g_fix_tok);
    cudaGetSymbolAddress((void**)&fcnt, g_fix_cnt);

    const int SM21 = 4 * (2 * PT_A + 1 * PT_B);   // 116736 (NPA=2,NPB=1)
    const int SM11 = 4 * (1 * PT_A + 1 * PT_B);   //  75776 (NPA=1,NPB=1)
    const int SM22 = 4 * (2 * PT_A + 2 * PT_B);   // 151552 (NPA=2,NPB=2)
    static int smem_set = 0;
    if (!smem_set) {
        cudaFuncSetAttribute(tc_gemm<2,1,2,4>, cudaFuncAttributeMaxDynamicSharedMemorySize, SM21);
        cudaFuncSetAttribute(tc_gemm<1,1,1,4>, cudaFuncAttributeMaxDynamicSharedMemorySize, SM11);
        cudaFuncSetAttribute(tc_gemm<1,1,2,4>, cudaFuncAttributeMaxDynamicSharedMemorySize, SM11);
        cudaFuncSetAttribute(tc_gemm<1,1,0,4>, cudaFuncAttributeMaxDynamicSharedMemorySize, SM11);
        cudaFuncSetAttribute(tc_gemm<2,2,1,4>, cudaFuncAttributeMaxDynamicSharedMemorySize, SM22);
        smem_set = 1;
    }

    // 0) prep: x + router weights split2; expert weights hi-plane convert; table init
    split2_kernel<<<(ll)BT * CC / 1024, 256>>>(x,   xs,   (ll)BT * CC);
    split2_kernel<<<(ll)CC * HH / 1024, 256>>>(Wr1, wr1t, (ll)CC * HH);
    split2_kernel<<<(ll)HH * HH / 1024, 256>>>(Wr2, wr2t, (ll)HH * HH);
    cvt_kernel<<<(ll)EE * CC * HH / 1024, 256>>>(We1, we1t);
    cvt_kernel<<<(ll)EE * HH * CC / 1024, 256>>>(We2, we2t);
    init_fix_kernel<<<(NSLOT + 255) / 256, 256>>>(ftok, fcnt, stok);

    // 1) h1 = relu(x @ Wr1 + br1) : 2-combo (fullA x hiB), single-plane fp16 out
    tc_gemm<2,1,2,4><<<dim3((BT/128)*(HH/128), 1), 256, SM21>>>(
        xs, (ll)BT*CC, BT, wr1t, 0, br1, 0,
        h1s, 0, BT, nullptr, 0, HH, CC, BT/128, HH/128);

    // 2) h2 = relu(h1 @ Wr2 + br2) : 1-combo (hiA x hiB), split2 out
    tc_gemm<1,1,1,4><<<dim3((BT/128)*(HH/128), 1), 256, SM11>>>(
        h1s, 0, BT, wr2t, 0, br2, 0,
        h2s, (ll)BT*HH, BT, nullptr, 0, HH, HH, BT/128, HH/128);

    // 3) logits -> softmax -> top-2, flag marginal tokens (gap23 < 4e-3)
    router_topk2_kernel<<<(BT * 32) / 128, 128>>>(h2s, (ll)BT*HH, Wr3, br3, tp, te, ftok, fcnt);

    // 3b) near-exact (3-combo, err ~2^-22) fixup chain for flagged tokens
    tc_gemm<2,2,1,4><<<dim3((FIXCAP/128)*(HH/128), 1), 256, SM22>>>(
        xs, (ll)BT*CC, FIXCAP, wr1t, (ll)CC*HH, br1, 0,
        h1f, (ll)FIXCAP*HH, FIXCAP, ftok, FIXCAP, HH, CC, FIXCAP/128, HH/128);
    tc_gemm<2,2,1,4><<<dim3((FIXCAP/128)*(HH/128), 1), 256, SM22>>>(
        h1f, (ll)FIXCAP*HH, FIXCAP, wr2t, (ll)HH*HH, br2, 0,
        h2f, (ll)FIXCAP*HH, FIXCAP, nullptr, 0, HH, HH, FIXCAP/128, HH/128);
    router_fix_kernel<<<(FIXCAP * 32) / 128, 128>>>(h2f, (ll)FIXCAP*HH, Wr3, br3, ftok, tp, te);

    // 4) routing tables
    route_scan_kernel<<<BB, 256>>>(te, dest, stok);

    // 5) eh[e] = relu(gather(x) @ We1[e] + be1[e]) : 1-combo, single-plane out
    tc_gemm<1,1,2,4><<<dim3((ROWS_E/128)*(HH/128), EE), 256, SM11>>>(
        xs, 0, ROWS_E, we1t, 0, be1, HH,
        ehs, 0, ROWS_E, stok, ROWS_E, HH, CC, ROWS_E/128, HH/128);

    // 6) ey[e] = eh[e] @ We2[e] + be2[e] : 1-combo, fp32 out
    tc_gemm<1,1,0,4><<<dim3((ROWS_E/128)*(CC/128), EE), 256, SM11>>>(
        ehs, 0, ROWS_E, we2t, 0, be2, CC,
        ey, 0, ROWS_E, nullptr, 0, CC, HH, ROWS_E/128, CC/128);

    // 7) combine
    combine_kernel<<<BT, 256>>>(ey, tp, dest, out);
}